// round 5
// baseline (speedup 1.0000x reference)
#include <cuda_runtime.h>
#include <cuda_bf16.h>

// ---------------- problem constants ----------------
#define NMAX 100000
#define EMAX 1600000
#define INF 512
#define D1 64      // H1*F1 = 8*8
#define H1N 8
#define D2 40      // H2*F2 = 1*40

// ---------------- device scratch ----------------
__device__ __align__(16) float g_h1  [NMAX * D1];
__device__ __align__(16) float g_el1 [NMAX * H1N];
__device__ __align__(16) float g_er1 [NMAX * H1N];
__device__ __align__(16) float g_agg1[NMAX * D1];   // normalized layer1 output (pre-bias)
__device__ __align__(16) float g_h2  [NMAX * D2];
__device__ __align__(16) float g_el2 [NMAX];
__device__ __align__(16) float g_er2 [NMAX];
__device__ __align__(16) float g_agg2[NMAX * D2];   // normalized layer2 output (pre-bias)
// CSR scratch
__device__ int g_hist[NMAX];
__device__ int g_rowstart[NMAX];
__device__ int g_cursor[NMAX];       // after scatter: row end
__device__ int g_sorted[EMAX];       // src ids grouped by dst
__device__ int g_counter;

// ---------------- helpers ----------------
__device__ __forceinline__ unsigned long long pk(float a, float b) {
    unsigned long long r;
    asm("mov.b64 %0, {%1, %2};" : "=l"(r) : "f"(a), "f"(b));
    return r;
}
__device__ __forceinline__ float2 upk(unsigned long long v) {
    float2 r;
    asm("mov.b64 {%0, %1}, %2;" : "=f"(r.x), "=f"(r.y) : "l"(v));
    return r;
}
__device__ __forceinline__ void fma2(unsigned long long& d, unsigned long long a, unsigned long long b) {
    asm("fma.rn.f32x2 %0, %1, %2, %3;" : "=l"(d) : "l"(a), "l"(b), "l"(d));
}
__device__ __forceinline__ float lrelu(float v) { return v >= 0.f ? v : 0.2f * v; }
__device__ __forceinline__ float eluf(float v)  { return v > 0.f ? v : expm1f(v); }

// ---------------- K0: zero hist + counter ----------------
__global__ void k_zero(int n) {
    int i = blockIdx.x * 256 + threadIdx.x;
    if (i < n) g_hist[i] = 0;
    if (i == 0) g_counter = 0;
}

// ---------------- K_hist: in-degree histogram ----------------
__global__ __launch_bounds__(256) void k_hist(const int* __restrict__ dst, int e) {
    int i = blockIdx.x * 256 + threadIdx.x;
    if (i < e) atomicAdd(&g_hist[dst[i]], 1);
}

// ---------------- K_rowalloc: warp-scanned row offsets ----------------
__global__ __launch_bounds__(256) void k_rowalloc(int n) {
    int d = blockIdx.x * 256 + threadIdx.x;
    int lane = threadIdx.x & 31;
    int c = (d < n) ? g_hist[d] : 0;
    int sum = c;
#pragma unroll
    for (int off = 1; off < 32; off <<= 1) {
        int v = __shfl_up_sync(0xffffffffu, sum, off);
        if (lane >= off) sum += v;
    }
    int total = __shfl_sync(0xffffffffu, sum, 31);
    int base = 0;
    if (lane == 31) base = atomicAdd(&g_counter, total);
    base = __shfl_sync(0xffffffffu, base, 31);
    if (d < n) {
        int st = base + sum - c;
        g_rowstart[d] = st;
        g_cursor[d]   = st;
    }
}

// ---------------- K_scatter: group src by dst ----------------
__global__ __launch_bounds__(256) void k_scatter(const int* __restrict__ src,
                                                 const int* __restrict__ dst, int e) {
    int i = blockIdx.x * 256 + threadIdx.x;
    if (i >= e) return;
    int p = atomicAdd(&g_cursor[dst[i]], 1);
    g_sorted[p] = src[i];
}

// ---------------- K1: h1 = x @ W1   (100k x 512) @ (512 x 64), f32x2 FMA ----------------
__global__ __launch_bounds__(256) void k_gemm1(const float* __restrict__ x,
                                               const float* __restrict__ W1, int n) {
    __shared__ __align__(16) float xs[128][40];
    __shared__ __align__(16) float ws[32][64];
    const int tx = threadIdx.x;
    const int row0 = blockIdx.x * 128;
    const int rg = (tx >> 3) * 4;
    const int cg = (tx & 7) * 8;

    unsigned long long acc[4][4];
#pragma unroll
    for (int i = 0; i < 4; i++)
#pragma unroll
        for (int j = 0; j < 4; j++) acc[i][j] = 0ull;

    for (int k0 = 0; k0 < INF; k0 += 32) {
#pragma unroll
        for (int it = 0; it < 4; it++) {
            int slot = tx + it * 256;
            int r = slot >> 3;
            int kk = (slot & 7) << 2;
            float4 v = make_float4(0.f, 0.f, 0.f, 0.f);
            int grow = row0 + r;
            if (grow < n) v = *(const float4*)(x + (size_t)grow * INF + k0 + kk);
            *(float4*)&xs[r][kk] = v;
        }
#pragma unroll
        for (int it = 0; it < 2; it++) {
            int slot = tx + it * 256;
            int kk = slot >> 4;
            int cc = (slot & 15) << 2;
            *(float4*)&ws[kk][cc] = *(const float4*)(W1 + (size_t)(k0 + kk) * D1 + cc);
        }
        __syncthreads();

#pragma unroll
        for (int k4 = 0; k4 < 32; k4 += 4) {
            float4 A[4];
#pragma unroll
            for (int i = 0; i < 4; i++) A[i] = *(const float4*)&xs[rg + i][k4];
#pragma unroll
            for (int kk = 0; kk < 4; kk++) {
                ulonglong2 B0 = *(const ulonglong2*)&ws[k4 + kk][cg];
                ulonglong2 B1 = *(const ulonglong2*)&ws[k4 + kk][cg + 4];
#pragma unroll
                for (int i = 0; i < 4; i++) {
                    float ai = ((const float*)&A[i])[kk];
                    unsigned long long pa = pk(ai, ai);
                    fma2(acc[i][0], pa, B0.x);
                    fma2(acc[i][1], pa, B0.y);
                    fma2(acc[i][2], pa, B1.x);
                    fma2(acc[i][3], pa, B1.y);
                }
            }
        }
        __syncthreads();
    }

#pragma unroll
    for (int i = 0; i < 4; i++) {
        int grow = row0 + rg + i;
        if (grow < n) {
            float2 v0 = upk(acc[i][0]), v1 = upk(acc[i][1]);
            float2 v2 = upk(acc[i][2]), v3 = upk(acc[i][3]);
            *(float4*)(g_h1 + (size_t)grow * D1 + cg)     = make_float4(v0.x, v0.y, v1.x, v1.y);
            *(float4*)(g_h1 + (size_t)grow * D1 + cg + 4) = make_float4(v2.x, v2.y, v3.x, v3.y);
        }
    }
}

// ---------------- K2: per-node attention dots el1/er1 ----------------
__global__ __launch_bounds__(256) void k_el1(const float* __restrict__ al1,
                                             const float* __restrict__ ar1, int n) {
    __shared__ float sa[64], sr[64];
    if (threadIdx.x < 64) { sa[threadIdx.x] = al1[threadIdx.x]; sr[threadIdx.x] = ar1[threadIdx.x]; }
    __syncthreads();
    int nid = blockIdx.x * 256 + threadIdx.x;
    if (nid >= n) return;
    const float4* hp = (const float4*)(g_h1 + (size_t)nid * D1);
    float el[8], er[8];
#pragma unroll
    for (int h = 0; h < 8; h++) {
        float4 t0 = hp[h * 2], t1 = hp[h * 2 + 1];
        int b = h * 8;
        el[h] = t0.x*sa[b] + t0.y*sa[b+1] + t0.z*sa[b+2] + t0.w*sa[b+3]
              + t1.x*sa[b+4] + t1.y*sa[b+5] + t1.z*sa[b+6] + t1.w*sa[b+7];
        er[h] = t0.x*sr[b] + t0.y*sr[b+1] + t0.z*sr[b+2] + t0.w*sr[b+3]
              + t1.x*sr[b+4] + t1.y*sr[b+5] + t1.z*sr[b+6] + t1.w*sr[b+7];
    }
    *(float4*)(g_el1 + (size_t)nid * 8)     = make_float4(el[0], el[1], el[2], el[3]);
    *(float4*)(g_el1 + (size_t)nid * 8 + 4) = make_float4(el[4], el[5], el[6], el[7]);
    *(float4*)(g_er1 + (size_t)nid * 8)     = make_float4(er[0], er[1], er[2], er[3]);
    *(float4*)(g_er1 + (size_t)nid * 8 + 4) = make_float4(er[4], er[5], er[6], er[7]);
}

// ---------------- K3: layer1 CSR aggregation (half-warp per dst) ----------------
// agg1[d] = (sum_e ex * h1[s]) / (sum_e ex), normalized in registers.
__global__ __launch_bounds__(256) void k_agg1(int n) {
    int t = blockIdx.x * 256 + threadIdx.x;
    int d = t >> 4;
    if (d >= n) return;
    int j = t & 15;          // float4 slot
    int h = j >> 1;          // head
    float er = g_er1[(size_t)d * 8 + h];
    int k0 = g_rowstart[d], k1 = g_cursor[d];
    float4 acc = make_float4(0.f, 0.f, 0.f, 0.f);
    float denom = 0.f;
    for (int k = k0; k < k1; k++) {
        int s = __ldg(g_sorted + k);
        float ex = __expf(lrelu(__ldg(g_el1 + (size_t)s * 8 + h) + er));
        float4 hv = __ldg((const float4*)(g_h1 + (size_t)s * D1) + j);
        acc.x = fmaf(ex, hv.x, acc.x);
        acc.y = fmaf(ex, hv.y, acc.y);
        acc.z = fmaf(ex, hv.z, acc.z);
        acc.w = fmaf(ex, hv.w, acc.w);
        denom += ex;
    }
    float iv = denom > 0.f ? __fdividef(1.f, denom) : 0.f;
    *(float4*)(g_agg1 + (size_t)d * D1 + j * 4) =
        make_float4(acc.x * iv, acc.y * iv, acc.z * iv, acc.w * iv);
}

// ---------------- K4: node: ELU(agg1 + b1), GEMM2 (64->40), el2/er2 ----------------
__global__ __launch_bounds__(256) void k_node2(const float* __restrict__ W2,
                                               const float* __restrict__ al2,
                                               const float* __restrict__ ar2,
                                               const float* __restrict__ b1, int n) {
    __shared__ float w2s[64 * 40];
    __shared__ float sal[40], sar[40], sb1[64];
    for (int i = threadIdx.x; i < 64 * 40; i += 256) w2s[i] = W2[i];
    if (threadIdx.x < 40) { sal[threadIdx.x] = al2[threadIdx.x]; sar[threadIdx.x] = ar2[threadIdx.x]; }
    if (threadIdx.x < 64) sb1[threadIdx.x] = b1[threadIdx.x];
    __syncthreads();
    int nid = blockIdx.x * 256 + threadIdx.x;
    if (nid >= n) return;

    float v[64];
    const float4* ap = (const float4*)(g_agg1 + (size_t)nid * D1);
#pragma unroll
    for (int j = 0; j < 16; j++) {
        float4 t = ap[j];
        v[j * 4 + 0] = eluf(t.x + sb1[j * 4 + 0]);
        v[j * 4 + 1] = eluf(t.y + sb1[j * 4 + 1]);
        v[j * 4 + 2] = eluf(t.z + sb1[j * 4 + 2]);
        v[j * 4 + 3] = eluf(t.w + sb1[j * 4 + 3]);
    }
    float ela = 0.f, era = 0.f;
    float* hp = g_h2 + (size_t)nid * D2;
    for (int c = 0; c < D2; c++) {
        float acc = 0.f;
#pragma unroll
        for (int k = 0; k < 64; k++) acc = fmaf(v[k], w2s[k * D2 + c], acc);
        hp[c] = acc;
        ela = fmaf(acc, sal[c], ela);
        era = fmaf(acc, sar[c], era);
    }
    g_el2[nid] = ela;
    g_er2[nid] = era;
}

// ---------------- K5: layer2 CSR aggregation (warp per dst, 20 lanes) ----------------
__global__ __launch_bounds__(256) void k_agg2(int n) {
    int d = (blockIdx.x * 256 + threadIdx.x) >> 5;
    int lane = threadIdx.x & 31;
    if (d >= n || lane >= 20) return;
    float er = g_er2[d];
    int k0 = g_rowstart[d], k1 = g_cursor[d];
    float2 acc = make_float2(0.f, 0.f);
    float denom = 0.f;
    for (int k = k0; k < k1; k++) {
        int s = __ldg(g_sorted + k);
        float ex = __expf(lrelu(__ldg(g_el2 + s) + er));
        float2 hv = __ldg((const float2*)(g_h2 + (size_t)s * D2) + lane);
        acc.x = fmaf(ex, hv.x, acc.x);
        acc.y = fmaf(ex, hv.y, acc.y);
        denom += ex;
    }
    float iv = denom > 0.f ? __fdividef(1.f, denom) : 0.f;
    *(float2*)(g_agg2 + (size_t)d * D2 + lane * 2) = make_float2(acc.x * iv, acc.y * iv);
}

// ---------------- K6: final: (agg2 + b2) then log_softmax ----------------
__global__ __launch_bounds__(256) void k_lsm(const float* __restrict__ b2,
                                             float* __restrict__ out, int n) {
    __shared__ float sb2[40];
    if (threadIdx.x < 40) sb2[threadIdx.x] = b2[threadIdx.x];
    __syncthreads();
    int nid = blockIdx.x * 256 + threadIdx.x;
    if (nid >= n) return;
    float v[40];
    const float4* ap = (const float4*)(g_agg2 + (size_t)nid * D2);
    float m = -1e30f;
#pragma unroll
    for (int j = 0; j < 10; j++) {
        float4 t = ap[j];
        v[j*4+0] = t.x + sb2[j*4+0];
        v[j*4+1] = t.y + sb2[j*4+1];
        v[j*4+2] = t.z + sb2[j*4+2];
        v[j*4+3] = t.w + sb2[j*4+3];
        m = fmaxf(m, fmaxf(fmaxf(v[j*4+0], v[j*4+1]), fmaxf(v[j*4+2], v[j*4+3])));
    }
    float s = 0.f;
#pragma unroll
    for (int j = 0; j < 40; j++) s += __expf(v[j] - m);
    float lse = m + logf(s);
    float4* op = (float4*)(out + (size_t)nid * D2);
#pragma unroll
    for (int j = 0; j < 10; j++)
        op[j] = make_float4(v[j*4+0] - lse, v[j*4+1] - lse, v[j*4+2] - lse, v[j*4+3] - lse);
}

// ---------------- launch ----------------
extern "C" void kernel_launch(void* const* d_in, const int* in_sizes, int n_in,
                              void* d_out, int out_size) {
    const float* x   = (const float*)d_in[0];
    const int*   src = (const int*)d_in[1];
    const int*   dst = (const int*)d_in[2];
    const float* W1  = (const float*)d_in[3];
    const float* al1 = (const float*)d_in[4];
    const float* ar1 = (const float*)d_in[5];
    const float* b1  = (const float*)d_in[6];
    const float* W2  = (const float*)d_in[7];
    const float* al2 = (const float*)d_in[8];
    const float* ar2 = (const float*)d_in[9];
    const float* b2  = (const float*)d_in[10];

    int n = in_sizes[0] / INF;
    int e = in_sizes[1];

    int nb_node  = (n + 255) / 256;
    int nb_edge  = (e + 255) / 256;
    int nb_gemm  = (n + 127) / 128;
    int nb_agg1  = (n * 16 + 255) / 256;
    int nb_agg2  = (n * 32 + 255) / 256;

    k_zero    <<<nb_node, 256>>>(n);
    k_hist    <<<nb_edge, 256>>>(dst, e);
    k_rowalloc<<<nb_node, 256>>>(n);
    k_scatter <<<nb_edge, 256>>>(src, dst, e);
    k_gemm1   <<<nb_gemm, 256>>>(x, W1, n);
    k_el1     <<<nb_node, 256>>>(al1, ar1, n);
    k_agg1    <<<nb_agg1, 256>>>(n);
    k_node2   <<<nb_node, 256>>>(W2, al2, ar2, b1, n);
    k_agg2    <<<nb_agg2, 256>>>(n);
    k_lsm     <<<nb_node, 256>>>(b2, (float*)d_out, n);
}

// round 6
// speedup vs baseline: 1.0515x; 1.0515x over previous
#include <cuda_runtime.h>
#include <cuda_bf16.h>

// ---------------- problem constants ----------------
#define NMAX 100000
#define EMAX 1600000
#define INF 512
#define D1 64      // H1*F1 = 8*8
#define H1N 8
#define D2 40      // H2*F2 = 1*40

// ---------------- device scratch ----------------
__device__ __align__(16) float g_h1  [NMAX * D1];
__device__ __align__(16) float g_el1 [NMAX * H1N];
__device__ __align__(16) float g_er1 [NMAX * H1N];
__device__ __align__(16) float g_agg1[NMAX * D1];   // normalized layer1 output (pre-bias)
__device__ __align__(16) float g_h2  [NMAX * D2];
__device__ __align__(16) float g_el2 [NMAX];
__device__ __align__(16) float g_er2 [NMAX];
__device__ __align__(16) float g_agg2[NMAX * D2];   // normalized layer2 output (pre-bias)
// CSR scratch
__device__ int g_hist[NMAX];
__device__ int g_rowstart[NMAX];
__device__ int g_cursor[NMAX];       // after scatter: row end
__device__ int g_sorted[EMAX];       // src ids grouped by dst
__device__ int g_counter;

// ---------------- helpers ----------------
__device__ __forceinline__ unsigned long long pk(float a, float b) {
    unsigned long long r;
    asm("mov.b64 %0, {%1, %2};" : "=l"(r) : "f"(a), "f"(b));
    return r;
}
__device__ __forceinline__ float2 upk(unsigned long long v) {
    float2 r;
    asm("mov.b64 {%0, %1}, %2;" : "=f"(r.x), "=f"(r.y) : "l"(v));
    return r;
}
__device__ __forceinline__ void fma2(unsigned long long& d, unsigned long long a, unsigned long long b) {
    asm("fma.rn.f32x2 %0, %1, %2, %3;" : "=l"(d) : "l"(a), "l"(b), "l"(d));
}
__device__ __forceinline__ float lrelu(float v) { return v >= 0.f ? v : 0.2f * v; }
__device__ __forceinline__ float eluf(float v)  { return v > 0.f ? v : expm1f(v); }

// ---------------- K0: zero hist + counter ----------------
__global__ void k_zero(int n) {
    int i = blockIdx.x * 256 + threadIdx.x;
    if (i < n) g_hist[i] = 0;
    if (i == 0) g_counter = 0;
}

// ---------------- K_hist: in-degree histogram ----------------
__global__ __launch_bounds__(256) void k_hist(const int* __restrict__ dst, int e) {
    int i = blockIdx.x * 256 + threadIdx.x;
    if (i < e) atomicAdd(&g_hist[dst[i]], 1);
}

// ---------------- K_rowalloc: warp-scanned row offsets ----------------
__global__ __launch_bounds__(256) void k_rowalloc(int n) {
    int d = blockIdx.x * 256 + threadIdx.x;
    int lane = threadIdx.x & 31;
    int c = (d < n) ? g_hist[d] : 0;
    int sum = c;
#pragma unroll
    for (int off = 1; off < 32; off <<= 1) {
        int v = __shfl_up_sync(0xffffffffu, sum, off);
        if (lane >= off) sum += v;
    }
    int total = __shfl_sync(0xffffffffu, sum, 31);
    int base = 0;
    if (lane == 31) base = atomicAdd(&g_counter, total);
    base = __shfl_sync(0xffffffffu, base, 31);
    if (d < n) {
        int st = base + sum - c;
        g_rowstart[d] = st;
        g_cursor[d]   = st;
    }
}

// ---------------- K_scatter: group src by dst ----------------
__global__ __launch_bounds__(256) void k_scatter(const int* __restrict__ src,
                                                 const int* __restrict__ dst, int e) {
    int i = blockIdx.x * 256 + threadIdx.x;
    if (i >= e) return;
    int p = atomicAdd(&g_cursor[dst[i]], 1);
    g_sorted[p] = src[i];
}

// ---------------- K1: h1 = x @ W1   (100k x 512) @ (512 x 64), f32x2 FMA ----------------
__global__ __launch_bounds__(256) void k_gemm1(const float* __restrict__ x,
                                               const float* __restrict__ W1, int n) {
    __shared__ __align__(16) float xs[128][40];
    __shared__ __align__(16) float ws[32][64];
    const int tx = threadIdx.x;
    const int row0 = blockIdx.x * 128;
    const int rg = (tx >> 3) * 4;
    const int cg = (tx & 7) * 8;

    unsigned long long acc[4][4];
#pragma unroll
    for (int i = 0; i < 4; i++)
#pragma unroll
        for (int j = 0; j < 4; j++) acc[i][j] = 0ull;

    for (int k0 = 0; k0 < INF; k0 += 32) {
#pragma unroll
        for (int it = 0; it < 4; it++) {
            int slot = tx + it * 256;
            int r = slot >> 3;
            int kk = (slot & 7) << 2;
            float4 v = make_float4(0.f, 0.f, 0.f, 0.f);
            int grow = row0 + r;
            if (grow < n) v = *(const float4*)(x + (size_t)grow * INF + k0 + kk);
            *(float4*)&xs[r][kk] = v;
        }
#pragma unroll
        for (int it = 0; it < 2; it++) {
            int slot = tx + it * 256;
            int kk = slot >> 4;
            int cc = (slot & 15) << 2;
            *(float4*)&ws[kk][cc] = *(const float4*)(W1 + (size_t)(k0 + kk) * D1 + cc);
        }
        __syncthreads();

#pragma unroll
        for (int k4 = 0; k4 < 32; k4 += 4) {
            float4 A[4];
#pragma unroll
            for (int i = 0; i < 4; i++) A[i] = *(const float4*)&xs[rg + i][k4];
#pragma unroll
            for (int kk = 0; kk < 4; kk++) {
                ulonglong2 B0 = *(const ulonglong2*)&ws[k4 + kk][cg];
                ulonglong2 B1 = *(const ulonglong2*)&ws[k4 + kk][cg + 4];
#pragma unroll
                for (int i = 0; i < 4; i++) {
                    float ai = ((const float*)&A[i])[kk];
                    unsigned long long pa = pk(ai, ai);
                    fma2(acc[i][0], pa, B0.x);
                    fma2(acc[i][1], pa, B0.y);
                    fma2(acc[i][2], pa, B1.x);
                    fma2(acc[i][3], pa, B1.y);
                }
            }
        }
        __syncthreads();
    }

#pragma unroll
    for (int i = 0; i < 4; i++) {
        int grow = row0 + rg + i;
        if (grow < n) {
            float2 v0 = upk(acc[i][0]), v1 = upk(acc[i][1]);
            float2 v2 = upk(acc[i][2]), v3 = upk(acc[i][3]);
            *(float4*)(g_h1 + (size_t)grow * D1 + cg)     = make_float4(v0.x, v0.y, v1.x, v1.y);
            *(float4*)(g_h1 + (size_t)grow * D1 + cg + 4) = make_float4(v2.x, v2.y, v3.x, v3.y);
        }
    }
}

// ---------------- K2: per-node attention dots el1/er1 ----------------
__global__ __launch_bounds__(256) void k_el1(const float* __restrict__ al1,
                                             const float* __restrict__ ar1, int n) {
    __shared__ float sa[64], sr[64];
    if (threadIdx.x < 64) { sa[threadIdx.x] = al1[threadIdx.x]; sr[threadIdx.x] = ar1[threadIdx.x]; }
    __syncthreads();
    int nid = blockIdx.x * 256 + threadIdx.x;
    if (nid >= n) return;
    const float4* hp = (const float4*)(g_h1 + (size_t)nid * D1);
    float el[8], er[8];
#pragma unroll
    for (int h = 0; h < 8; h++) {
        float4 t0 = hp[h * 2], t1 = hp[h * 2 + 1];
        int b = h * 8;
        el[h] = t0.x*sa[b] + t0.y*sa[b+1] + t0.z*sa[b+2] + t0.w*sa[b+3]
              + t1.x*sa[b+4] + t1.y*sa[b+5] + t1.z*sa[b+6] + t1.w*sa[b+7];
        er[h] = t0.x*sr[b] + t0.y*sr[b+1] + t0.z*sr[b+2] + t0.w*sr[b+3]
              + t1.x*sr[b+4] + t1.y*sr[b+5] + t1.z*sr[b+6] + t1.w*sr[b+7];
    }
    *(float4*)(g_el1 + (size_t)nid * 8)     = make_float4(el[0], el[1], el[2], el[3]);
    *(float4*)(g_el1 + (size_t)nid * 8 + 4) = make_float4(el[4], el[5], el[6], el[7]);
    *(float4*)(g_er1 + (size_t)nid * 8)     = make_float4(er[0], er[1], er[2], er[3]);
    *(float4*)(g_er1 + (size_t)nid * 8 + 4) = make_float4(er[4], er[5], er[6], er[7]);
}

// ---------------- K3: layer1 CSR aggregation (half-warp per dst) ----------------
// agg1[d] = (sum_e ex * h1[s]) / (sum_e ex), normalized in registers.
__global__ __launch_bounds__(256) void k_agg1(int n) {
    int t = blockIdx.x * 256 + threadIdx.x;
    int d = t >> 4;
    if (d >= n) return;
    int j = t & 15;          // float4 slot
    int h = j >> 1;          // head
    float er = g_er1[(size_t)d * 8 + h];
    int k0 = g_rowstart[d], k1 = g_cursor[d];
    float4 acc = make_float4(0.f, 0.f, 0.f, 0.f);
    float denom = 0.f;
    for (int k = k0; k < k1; k++) {
        int s = __ldg(g_sorted + k);
        float ex = __expf(lrelu(__ldg(g_el1 + (size_t)s * 8 + h) + er));
        float4 hv = __ldg((const float4*)(g_h1 + (size_t)s * D1) + j);
        acc.x = fmaf(ex, hv.x, acc.x);
        acc.y = fmaf(ex, hv.y, acc.y);
        acc.z = fmaf(ex, hv.z, acc.z);
        acc.w = fmaf(ex, hv.w, acc.w);
        denom += ex;
    }
    float iv = denom > 0.f ? __fdividef(1.f, denom) : 0.f;
    *(float4*)(g_agg1 + (size_t)d * D1 + j * 4) =
        make_float4(acc.x * iv, acc.y * iv, acc.z * iv, acc.w * iv);
}

// ---------------- K4: node: ELU(agg1 + b1), GEMM2 (64->40), el2/er2 ----------------
__global__ __launch_bounds__(256) void k_node2(const float* __restrict__ W2,
                                               const float* __restrict__ al2,
                                               const float* __restrict__ ar2,
                                               const float* __restrict__ b1, int n) {
    __shared__ float w2s[64 * 40];
    __shared__ float sal[40], sar[40], sb1[64];
    for (int i = threadIdx.x; i < 64 * 40; i += 256) w2s[i] = W2[i];
    if (threadIdx.x < 40) { sal[threadIdx.x] = al2[threadIdx.x]; sar[threadIdx.x] = ar2[threadIdx.x]; }
    if (threadIdx.x < 64) sb1[threadIdx.x] = b1[threadIdx.x];
    __syncthreads();
    int nid = blockIdx.x * 256 + threadIdx.x;
    if (nid >= n) return;

    float v[64];
    const float4* ap = (const float4*)(g_agg1 + (size_t)nid * D1);
#pragma unroll
    for (int j = 0; j < 16; j++) {
        float4 t = ap[j];
        v[j * 4 + 0] = eluf(t.x + sb1[j * 4 + 0]);
        v[j * 4 + 1] = eluf(t.y + sb1[j * 4 + 1]);
        v[j * 4 + 2] = eluf(t.z + sb1[j * 4 + 2]);
        v[j * 4 + 3] = eluf(t.w + sb1[j * 4 + 3]);
    }
    float ela = 0.f, era = 0.f;
    float* hp = g_h2 + (size_t)nid * D2;
    for (int c = 0; c < D2; c++) {
        float acc = 0.f;
#pragma unroll
        for (int k = 0; k < 64; k++) acc = fmaf(v[k], w2s[k * D2 + c], acc);
        hp[c] = acc;
        ela = fmaf(acc, sal[c], ela);
        era = fmaf(acc, sar[c], era);
    }
    g_el2[nid] = ela;
    g_er2[nid] = era;
}

// ---------------- K5: layer2 CSR aggregation (warp per dst, 20 lanes) ----------------
__global__ __launch_bounds__(256) void k_agg2(int n) {
    int d = (blockIdx.x * 256 + threadIdx.x) >> 5;
    int lane = threadIdx.x & 31;
    if (d >= n || lane >= 20) return;
    float er = g_er2[d];
    int k0 = g_rowstart[d], k1 = g_cursor[d];
    float2 acc = make_float2(0.f, 0.f);
    float denom = 0.f;
    for (int k = k0; k < k1; k++) {
        int s = __ldg(g_sorted + k);
        float ex = __expf(lrelu(__ldg(g_el2 + s) + er));
        float2 hv = __ldg((const float2*)(g_h2 + (size_t)s * D2) + lane);
        acc.x = fmaf(ex, hv.x, acc.x);
        acc.y = fmaf(ex, hv.y, acc.y);
        denom += ex;
    }
    float iv = denom > 0.f ? __fdividef(1.f, denom) : 0.f;
    *(float2*)(g_agg2 + (size_t)d * D2 + lane * 2) = make_float2(acc.x * iv, acc.y * iv);
}

// ---------------- K6: final: (agg2 + b2) then log_softmax ----------------
__global__ __launch_bounds__(256) void k_lsm(const float* __restrict__ b2,
                                             float* __restrict__ out, int n) {
    __shared__ float sb2[40];
    if (threadIdx.x < 40) sb2[threadIdx.x] = b2[threadIdx.x];
    __syncthreads();
    int nid = blockIdx.x * 256 + threadIdx.x;
    if (nid >= n) return;
    float v[40];
    const float4* ap = (const float4*)(g_agg2 + (size_t)nid * D2);
    float m = -1e30f;
#pragma unroll
    for (int j = 0; j < 10; j++) {
        float4 t = ap[j];
        v[j*4+0] = t.x + sb2[j*4+0];
        v[j*4+1] = t.y + sb2[j*4+1];
        v[j*4+2] = t.z + sb2[j*4+2];
        v[j*4+3] = t.w + sb2[j*4+3];
        m = fmaxf(m, fmaxf(fmaxf(v[j*4+0], v[j*4+1]), fmaxf(v[j*4+2], v[j*4+3])));
    }
    float s = 0.f;
#pragma unroll
    for (int j = 0; j < 40; j++) s += __expf(v[j] - m);
    float lse = m + logf(s);
    float4* op = (float4*)(out + (size_t)nid * D2);
#pragma unroll
    for (int j = 0; j < 10; j++)
        op[j] = make_float4(v[j*4+0] - lse, v[j*4+1] - lse, v[j*4+2] - lse, v[j*4+3] - lse);
}

// ---------------- launch ----------------
extern "C" void kernel_launch(void* const* d_in, const int* in_sizes, int n_in,
                              void* d_out, int out_size) {
    const float* x   = (const float*)d_in[0];
    const int*   src = (const int*)d_in[1];
    const int*   dst = (const int*)d_in[2];
    const float* W1  = (const float*)d_in[3];
    const float* al1 = (const float*)d_in[4];
    const float* ar1 = (const float*)d_in[5];
    const float* b1  = (const float*)d_in[6];
    const float* W2  = (const float*)d_in[7];
    const float* al2 = (const float*)d_in[8];
    const float* ar2 = (const float*)d_in[9];
    const float* b2  = (const float*)d_in[10];

    int n = in_sizes[0] / INF;
    int e = in_sizes[1];

    int nb_node  = (n + 255) / 256;
    int nb_edge  = (e + 255) / 256;
    int nb_gemm  = (n + 127) / 128;
    int nb_agg1  = (n * 16 + 255) / 256;
    int nb_agg2  = (n * 32 + 255) / 256;

    k_zero    <<<nb_node, 256>>>(n);
    k_hist    <<<nb_edge, 256>>>(dst, e);
    k_rowalloc<<<nb_node, 256>>>(n);
    k_scatter <<<nb_edge, 256>>>(src, dst, e);
    k_gemm1   <<<nb_gemm, 256>>>(x, W1, n);
    k_el1     <<<nb_node, 256>>>(al1, ar1, n);
    k_agg1    <<<nb_agg1, 256>>>(n);
    k_node2   <<<nb_node, 256>>>(W2, al2, ar2, b1, n);
    k_agg2    <<<nb_agg2, 256>>>(n);
    k_lsm     <<<nb_node, 256>>>(b2, (float*)d_out, n);
}

// round 7
// speedup vs baseline: 1.0515x; 1.0001x over previous
#include <cuda_runtime.h>
#include <cuda_bf16.h>

// ---------------- problem constants ----------------
#define NMAX 100000
#define EMAX 1600000
#define INF 512
#define D1 64      // H1*F1 = 8*8
#define H1N 8
#define D2 40      // H2*F2 = 1*40

// ---------------- device scratch ----------------
__device__ __align__(16) float g_h1  [NMAX * D1];
__device__ __align__(16) float g_el1 [NMAX * H1N];
__device__ __align__(16) float g_er1 [NMAX * H1N];
__device__ __align__(16) float g_agg1[NMAX * D1];   // normalized layer1 output (pre-bias)
__device__ __align__(16) float g_h2  [NMAX * D2];
__device__ __align__(16) float g_el2 [NMAX];
__device__ __align__(16) float g_er2 [NMAX];
__device__ __align__(16) float g_agg2[NMAX * D2];   // normalized layer2 output (pre-bias)
// CSR scratch
__device__ int g_hist[NMAX];
__device__ int g_rowstart[NMAX];
__device__ int g_cursor[NMAX];       // after scatter: row end
__device__ int g_sorted[EMAX];       // src ids grouped by dst
__device__ int g_counter;

// ---------------- helpers ----------------
__device__ __forceinline__ unsigned long long pk(float a, float b) {
    unsigned long long r;
    asm("mov.b64 %0, {%1, %2};" : "=l"(r) : "f"(a), "f"(b));
    return r;
}
__device__ __forceinline__ float2 upk(unsigned long long v) {
    float2 r;
    asm("mov.b64 {%0, %1}, %2;" : "=f"(r.x), "=f"(r.y) : "l"(v));
    return r;
}
__device__ __forceinline__ void fma2(unsigned long long& d, unsigned long long a, unsigned long long b) {
    asm("fma.rn.f32x2 %0, %1, %2, %3;" : "=l"(d) : "l"(a), "l"(b), "l"(d));
}
__device__ __forceinline__ float lrelu(float v) { return v >= 0.f ? v : 0.2f * v; }
__device__ __forceinline__ float eluf(float v)  { return v > 0.f ? v : expm1f(v); }

// ---------------- K0: zero hist + counter ----------------
__global__ void k_zero(int n) {
    int i = blockIdx.x * 256 + threadIdx.x;
    if (i < n) g_hist[i] = 0;
    if (i == 0) g_counter = 0;
}

// ---------------- K_hist: in-degree histogram ----------------
__global__ __launch_bounds__(256) void k_hist(const int* __restrict__ dst, int e) {
    int i = blockIdx.x * 256 + threadIdx.x;
    if (i < e) atomicAdd(&g_hist[dst[i]], 1);
}

// ---------------- K_rowalloc: warp-scanned row offsets ----------------
__global__ __launch_bounds__(256) void k_rowalloc(int n) {
    int d = blockIdx.x * 256 + threadIdx.x;
    int lane = threadIdx.x & 31;
    int c = (d < n) ? g_hist[d] : 0;
    int sum = c;
#pragma unroll
    for (int off = 1; off < 32; off <<= 1) {
        int v = __shfl_up_sync(0xffffffffu, sum, off);
        if (lane >= off) sum += v;
    }
    int total = __shfl_sync(0xffffffffu, sum, 31);
    int base = 0;
    if (lane == 31) base = atomicAdd(&g_counter, total);
    base = __shfl_sync(0xffffffffu, base, 31);
    if (d < n) {
        int st = base + sum - c;
        g_rowstart[d] = st;
        g_cursor[d]   = st;
    }
}

// ---------------- K_scatter: group src by dst ----------------
__global__ __launch_bounds__(256) void k_scatter(const int* __restrict__ src,
                                                 const int* __restrict__ dst, int e) {
    int i = blockIdx.x * 256 + threadIdx.x;
    if (i >= e) return;
    int p = atomicAdd(&g_cursor[dst[i]], 1);
    g_sorted[p] = src[i];
}

// ---------------- K1: h1 = x @ W1   (100k x 512) @ (512 x 64), f32x2 FMA ----------------
__global__ __launch_bounds__(256) void k_gemm1(const float* __restrict__ x,
                                               const float* __restrict__ W1, int n) {
    __shared__ __align__(16) float xs[128][40];
    __shared__ __align__(16) float ws[32][64];
    const int tx = threadIdx.x;
    const int row0 = blockIdx.x * 128;
    const int rg = (tx >> 3) * 4;
    const int cg = (tx & 7) * 8;

    unsigned long long acc[4][4];
#pragma unroll
    for (int i = 0; i < 4; i++)
#pragma unroll
        for (int j = 0; j < 4; j++) acc[i][j] = 0ull;

    for (int k0 = 0; k0 < INF; k0 += 32) {
#pragma unroll
        for (int it = 0; it < 4; it++) {
            int slot = tx + it * 256;
            int r = slot >> 3;
            int kk = (slot & 7) << 2;
            float4 v = make_float4(0.f, 0.f, 0.f, 0.f);
            int grow = row0 + r;
            if (grow < n) v = *(const float4*)(x + (size_t)grow * INF + k0 + kk);
            *(float4*)&xs[r][kk] = v;
        }
#pragma unroll
        for (int it = 0; it < 2; it++) {
            int slot = tx + it * 256;
            int kk = slot >> 4;
            int cc = (slot & 15) << 2;
            *(float4*)&ws[kk][cc] = *(const float4*)(W1 + (size_t)(k0 + kk) * D1 + cc);
        }
        __syncthreads();

#pragma unroll
        for (int k4 = 0; k4 < 32; k4 += 4) {
            float4 A[4];
#pragma unroll
            for (int i = 0; i < 4; i++) A[i] = *(const float4*)&xs[rg + i][k4];
#pragma unroll
            for (int kk = 0; kk < 4; kk++) {
                ulonglong2 B0 = *(const ulonglong2*)&ws[k4 + kk][cg];
                ulonglong2 B1 = *(const ulonglong2*)&ws[k4 + kk][cg + 4];
#pragma unroll
                for (int i = 0; i < 4; i++) {
                    float ai = ((const float*)&A[i])[kk];
                    unsigned long long pa = pk(ai, ai);
                    fma2(acc[i][0], pa, B0.x);
                    fma2(acc[i][1], pa, B0.y);
                    fma2(acc[i][2], pa, B1.x);
                    fma2(acc[i][3], pa, B1.y);
                }
            }
        }
        __syncthreads();
    }

#pragma unroll
    for (int i = 0; i < 4; i++) {
        int grow = row0 + rg + i;
        if (grow < n) {
            float2 v0 = upk(acc[i][0]), v1 = upk(acc[i][1]);
            float2 v2 = upk(acc[i][2]), v3 = upk(acc[i][3]);
            *(float4*)(g_h1 + (size_t)grow * D1 + cg)     = make_float4(v0.x, v0.y, v1.x, v1.y);
            *(float4*)(g_h1 + (size_t)grow * D1 + cg + 4) = make_float4(v2.x, v2.y, v3.x, v3.y);
        }
    }
}

// ---------------- K2: per-node attention dots el1/er1 ----------------
__global__ __launch_bounds__(256) void k_el1(const float* __restrict__ al1,
                                             const float* __restrict__ ar1, int n) {
    __shared__ float sa[64], sr[64];
    if (threadIdx.x < 64) { sa[threadIdx.x] = al1[threadIdx.x]; sr[threadIdx.x] = ar1[threadIdx.x]; }
    __syncthreads();
    int nid = blockIdx.x * 256 + threadIdx.x;
    if (nid >= n) return;
    const float4* hp = (const float4*)(g_h1 + (size_t)nid * D1);
    float el[8], er[8];
#pragma unroll
    for (int h = 0; h < 8; h++) {
        float4 t0 = hp[h * 2], t1 = hp[h * 2 + 1];
        int b = h * 8;
        el[h] = t0.x*sa[b] + t0.y*sa[b+1] + t0.z*sa[b+2] + t0.w*sa[b+3]
              + t1.x*sa[b+4] + t1.y*sa[b+5] + t1.z*sa[b+6] + t1.w*sa[b+7];
        er[h] = t0.x*sr[b] + t0.y*sr[b+1] + t0.z*sr[b+2] + t0.w*sr[b+3]
              + t1.x*sr[b+4] + t1.y*sr[b+5] + t1.z*sr[b+6] + t1.w*sr[b+7];
    }
    *(float4*)(g_el1 + (size_t)nid * 8)     = make_float4(el[0], el[1], el[2], el[3]);
    *(float4*)(g_el1 + (size_t)nid * 8 + 4) = make_float4(el[4], el[5], el[6], el[7]);
    *(float4*)(g_er1 + (size_t)nid * 8)     = make_float4(er[0], er[1], er[2], er[3]);
    *(float4*)(g_er1 + (size_t)nid * 8 + 4) = make_float4(er[4], er[5], er[6], er[7]);
}

// ---------------- K3: layer1 CSR aggregation (half-warp per dst) ----------------
// agg1[d] = (sum_e ex * h1[s]) / (sum_e ex), normalized in registers.
__global__ __launch_bounds__(256) void k_agg1(int n) {
    int t = blockIdx.x * 256 + threadIdx.x;
    int d = t >> 4;
    if (d >= n) return;
    int j = t & 15;          // float4 slot
    int h = j >> 1;          // head
    float er = g_er1[(size_t)d * 8 + h];
    int k0 = g_rowstart[d], k1 = g_cursor[d];
    float4 acc = make_float4(0.f, 0.f, 0.f, 0.f);
    float denom = 0.f;
    for (int k = k0; k < k1; k++) {
        int s = __ldg(g_sorted + k);
        float ex = __expf(lrelu(__ldg(g_el1 + (size_t)s * 8 + h) + er));
        float4 hv = __ldg((const float4*)(g_h1 + (size_t)s * D1) + j);
        acc.x = fmaf(ex, hv.x, acc.x);
        acc.y = fmaf(ex, hv.y, acc.y);
        acc.z = fmaf(ex, hv.z, acc.z);
        acc.w = fmaf(ex, hv.w, acc.w);
        denom += ex;
    }
    float iv = denom > 0.f ? __fdividef(1.f, denom) : 0.f;
    *(float4*)(g_agg1 + (size_t)d * D1 + j * 4) =
        make_float4(acc.x * iv, acc.y * iv, acc.z * iv, acc.w * iv);
}

// ---------------- K4: node: ELU(agg1 + b1), GEMM2 (64->40), el2/er2 ----------------
__global__ __launch_bounds__(256) void k_node2(const float* __restrict__ W2,
                                               const float* __restrict__ al2,
                                               const float* __restrict__ ar2,
                                               const float* __restrict__ b1, int n) {
    __shared__ float w2s[64 * 40];
    __shared__ float sal[40], sar[40], sb1[64];
    for (int i = threadIdx.x; i < 64 * 40; i += 256) w2s[i] = W2[i];
    if (threadIdx.x < 40) { sal[threadIdx.x] = al2[threadIdx.x]; sar[threadIdx.x] = ar2[threadIdx.x]; }
    if (threadIdx.x < 64) sb1[threadIdx.x] = b1[threadIdx.x];
    __syncthreads();
    int nid = blockIdx.x * 256 + threadIdx.x;
    if (nid >= n) return;

    float v[64];
    const float4* ap = (const float4*)(g_agg1 + (size_t)nid * D1);
#pragma unroll
    for (int j = 0; j < 16; j++) {
        float4 t = ap[j];
        v[j * 4 + 0] = eluf(t.x + sb1[j * 4 + 0]);
        v[j * 4 + 1] = eluf(t.y + sb1[j * 4 + 1]);
        v[j * 4 + 2] = eluf(t.z + sb1[j * 4 + 2]);
        v[j * 4 + 3] = eluf(t.w + sb1[j * 4 + 3]);
    }
    float ela = 0.f, era = 0.f;
    float* hp = g_h2 + (size_t)nid * D2;
    for (int c = 0; c < D2; c++) {
        float acc = 0.f;
#pragma unroll
        for (int k = 0; k < 64; k++) acc = fmaf(v[k], w2s[k * D2 + c], acc);
        hp[c] = acc;
        ela = fmaf(acc, sal[c], ela);
        era = fmaf(acc, sar[c], era);
    }
    g_el2[nid] = ela;
    g_er2[nid] = era;
}

// ---------------- K5: layer2 CSR aggregation (warp per dst, 20 lanes) ----------------
__global__ __launch_bounds__(256) void k_agg2(int n) {
    int d = (blockIdx.x * 256 + threadIdx.x) >> 5;
    int lane = threadIdx.x & 31;
    if (d >= n || lane >= 20) return;
    float er = g_er2[d];
    int k0 = g_rowstart[d], k1 = g_cursor[d];
    float2 acc = make_float2(0.f, 0.f);
    float denom = 0.f;
    for (int k = k0; k < k1; k++) {
        int s = __ldg(g_sorted + k);
        float ex = __expf(lrelu(__ldg(g_el2 + s) + er));
        float2 hv = __ldg((const float2*)(g_h2 + (size_t)s * D2) + lane);
        acc.x = fmaf(ex, hv.x, acc.x);
        acc.y = fmaf(ex, hv.y, acc.y);
        denom += ex;
    }
    float iv = denom > 0.f ? __fdividef(1.f, denom) : 0.f;
    *(float2*)(g_agg2 + (size_t)d * D2 + lane * 2) = make_float2(acc.x * iv, acc.y * iv);
}

// ---------------- K6: final: (agg2 + b2) then log_softmax ----------------
__global__ __launch_bounds__(256) void k_lsm(const float* __restrict__ b2,
                                             float* __restrict__ out, int n) {
    __shared__ float sb2[40];
    if (threadIdx.x < 40) sb2[threadIdx.x] = b2[threadIdx.x];
    __syncthreads();
    int nid = blockIdx.x * 256 + threadIdx.x;
    if (nid >= n) return;
    float v[40];
    const float4* ap = (const float4*)(g_agg2 + (size_t)nid * D2);
    float m = -1e30f;
#pragma unroll
    for (int j = 0; j < 10; j++) {
        float4 t = ap[j];
        v[j*4+0] = t.x + sb2[j*4+0];
        v[j*4+1] = t.y + sb2[j*4+1];
        v[j*4+2] = t.z + sb2[j*4+2];
        v[j*4+3] = t.w + sb2[j*4+3];
        m = fmaxf(m, fmaxf(fmaxf(v[j*4+0], v[j*4+1]), fmaxf(v[j*4+2], v[j*4+3])));
    }
    float s = 0.f;
#pragma unroll
    for (int j = 0; j < 40; j++) s += __expf(v[j] - m);
    float lse = m + logf(s);
    float4* op = (float4*)(out + (size_t)nid * D2);
#pragma unroll
    for (int j = 0; j < 10; j++)
        op[j] = make_float4(v[j*4+0] - lse, v[j*4+1] - lse, v[j*4+2] - lse, v[j*4+3] - lse);
}

// ---------------- launch ----------------
extern "C" void kernel_launch(void* const* d_in, const int* in_sizes, int n_in,
                              void* d_out, int out_size) {
    const float* x   = (const float*)d_in[0];
    const int*   src = (const int*)d_in[1];
    const int*   dst = (const int*)d_in[2];
    const float* W1  = (const float*)d_in[3];
    const float* al1 = (const float*)d_in[4];
    const float* ar1 = (const float*)d_in[5];
    const float* b1  = (const float*)d_in[6];
    const float* W2  = (const float*)d_in[7];
    const float* al2 = (const float*)d_in[8];
    const float* ar2 = (const float*)d_in[9];
    const float* b2  = (const float*)d_in[10];

    int n = in_sizes[0] / INF;
    int e = in_sizes[1];

    int nb_node  = (n + 255) / 256;
    int nb_edge  = (e + 255) / 256;
    int nb_gemm  = (n + 127) / 128;
    int nb_agg1  = (n * 16 + 255) / 256;
    int nb_agg2  = (n * 32 + 255) / 256;

    k_zero    <<<nb_node, 256>>>(n);
    k_hist    <<<nb_edge, 256>>>(dst, e);
    k_rowalloc<<<nb_node, 256>>>(n);
    k_scatter <<<nb_edge, 256>>>(src, dst, e);
    k_gemm1   <<<nb_gemm, 256>>>(x, W1, n);
    k_el1     <<<nb_node, 256>>>(al1, ar1, n);
    k_agg1    <<<nb_agg1, 256>>>(n);
    k_node2   <<<nb_node, 256>>>(W2, al2, ar2, b1, n);
    k_agg2    <<<nb_agg2, 256>>>(n);
    k_lsm     <<<nb_node, 256>>>(b2, (float*)d_out, n);
}

// round 8
// speedup vs baseline: 1.1389x; 1.0830x over previous
#include <cuda_runtime.h>
#include <cuda_fp16.h>

// ---------------- problem constants ----------------
#define NMAX 100000
#define EMAX 1600000
#define INF 512
#define D1 64      // H1*F1 = 8*8
#define H1N 8
#define D2 40      // H2*F2 = 1*40

// ---------------- device scratch ----------------
__device__ __align__(16) __half g_h1h [NMAX * D1];   // fp16 layer1 features (gather payload)
__device__ __align__(16) __half g_el1h[NMAX * H1N];  // fp16 src-side attention
__device__ __align__(16) float  g_er1 [NMAX * H1N];  // fp32 dst-side attention
__device__ __align__(16) float  g_agg1[NMAX * D1];   // normalized layer1 output (pre-bias)
__device__ __align__(16) __half g_h2h [NMAX * D2];   // fp16 layer2 features
__device__ __align__(16) __half g_el2h[NMAX];
__device__ __align__(16) float  g_er2 [NMAX];
__device__ __align__(16) float  g_agg2[NMAX * D2];   // normalized layer2 output (pre-bias)
// CSR scratch
__device__ int g_hist[NMAX];
__device__ int g_rowstart[NMAX];
__device__ int g_cursor[NMAX];
__device__ int g_sorted[EMAX];
__device__ int g_counter;

// ---------------- helpers ----------------
__device__ __forceinline__ unsigned long long pk(float a, float b) {
    unsigned long long r;
    asm("mov.b64 %0, {%1, %2};" : "=l"(r) : "f"(a), "f"(b));
    return r;
}
__device__ __forceinline__ float2 upk(unsigned long long v) {
    float2 r;
    asm("mov.b64 {%0, %1}, %2;" : "=f"(r.x), "=f"(r.y) : "l"(v));
    return r;
}
__device__ __forceinline__ void fma2(unsigned long long& d, unsigned long long a, unsigned long long b) {
    asm("fma.rn.f32x2 %0, %1, %2, %3;" : "=l"(d) : "l"(a), "l"(b), "l"(d));
}
__device__ __forceinline__ float lrelu(float v) { return v >= 0.f ? v : 0.2f * v; }
__device__ __forceinline__ float eluf(float v)  { return v > 0.f ? v : expm1f(v); }

// ---------------- K0: zero hist + counter ----------------
__global__ void k_zero(int n) {
    int i = blockIdx.x * 256 + threadIdx.x;
    if (i < n) g_hist[i] = 0;
    if (i == 0) g_counter = 0;
}

// ---------------- K_hist ----------------
__global__ __launch_bounds__(256) void k_hist(const int* __restrict__ dst, int e) {
    int i = blockIdx.x * 256 + threadIdx.x;
    if (i < e) atomicAdd(&g_hist[dst[i]], 1);
}

// ---------------- K_rowalloc: warp-scanned row offsets ----------------
__global__ __launch_bounds__(256) void k_rowalloc(int n) {
    int d = blockIdx.x * 256 + threadIdx.x;
    int lane = threadIdx.x & 31;
    int c = (d < n) ? g_hist[d] : 0;
    int sum = c;
#pragma unroll
    for (int off = 1; off < 32; off <<= 1) {
        int v = __shfl_up_sync(0xffffffffu, sum, off);
        if (lane >= off) sum += v;
    }
    int total = __shfl_sync(0xffffffffu, sum, 31);
    int base = 0;
    if (lane == 31) base = atomicAdd(&g_counter, total);
    base = __shfl_sync(0xffffffffu, base, 31);
    if (d < n) {
        int st = base + sum - c;
        g_rowstart[d] = st;
        g_cursor[d]   = st;
    }
}

// ---------------- K_scatter ----------------
__global__ __launch_bounds__(256) void k_scatter(const int* __restrict__ src,
                                                 const int* __restrict__ dst, int e) {
    int i = blockIdx.x * 256 + threadIdx.x;
    if (i >= e) return;
    int p = atomicAdd(&g_cursor[dst[i]], 1);
    g_sorted[p] = src[i];
}

// ---------------- K1: h1 = x @ W1, pipelined f32x2; fused el1/er1 + fp16 store ----------------
__global__ __launch_bounds__(256) void k_gemm1(const float* __restrict__ x,
                                               const float* __restrict__ W1,
                                               const float* __restrict__ al1,
                                               const float* __restrict__ ar1, int n) {
    __shared__ __align__(16) float xs[128][40];
    __shared__ __align__(16) float ws[32][64];
    const int tx = threadIdx.x;
    const int row0 = blockIdx.x * 128;
    const int rg = (tx >> 3) * 4;
    const int cg = (tx & 7) * 8;
    const int hc = tx & 7;            // head owned by this thread

    float4 xr[4];
    float4 wr[2];

    // prologue: load tile 0 -> regs -> smem
#pragma unroll
    for (int it = 0; it < 4; it++) {
        int slot = tx + it * 256;
        int r = slot >> 3;
        int kk = (slot & 7) << 2;
        int grow = row0 + r;
        xr[it] = (grow < n) ? *(const float4*)(x + (size_t)grow * INF + kk)
                            : make_float4(0.f, 0.f, 0.f, 0.f);
    }
#pragma unroll
    for (int it = 0; it < 2; it++) {
        int slot = tx + it * 256;
        int kk = slot >> 4;
        int cc = (slot & 15) << 2;
        wr[it] = *(const float4*)(W1 + (size_t)kk * D1 + cc);
    }
#pragma unroll
    for (int it = 0; it < 4; it++) {
        int slot = tx + it * 256;
        *(float4*)&xs[slot >> 3][(slot & 7) << 2] = xr[it];
    }
#pragma unroll
    for (int it = 0; it < 2; it++) {
        int slot = tx + it * 256;
        *(float4*)&ws[slot >> 4][(slot & 15) << 2] = wr[it];
    }
    __syncthreads();

    unsigned long long acc[4][4];
#pragma unroll
    for (int i = 0; i < 4; i++)
#pragma unroll
        for (int j = 0; j < 4; j++) acc[i][j] = 0ull;

    for (int t = 0; t < 16; t++) {
        // prefetch next tile into registers (overlaps with compute)
        if (t < 15) {
            int k0 = (t + 1) * 32;
#pragma unroll
            for (int it = 0; it < 4; it++) {
                int slot = tx + it * 256;
                int r = slot >> 3;
                int kk = (slot & 7) << 2;
                int grow = row0 + r;
                xr[it] = (grow < n) ? *(const float4*)(x + (size_t)grow * INF + k0 + kk)
                                    : make_float4(0.f, 0.f, 0.f, 0.f);
            }
#pragma unroll
            for (int it = 0; it < 2; it++) {
                int slot = tx + it * 256;
                int kk = slot >> 4;
                int cc = (slot & 15) << 2;
                wr[it] = *(const float4*)(W1 + (size_t)(k0 + kk) * D1 + cc);
            }
        }

        // compute current tile
#pragma unroll
        for (int k4 = 0; k4 < 32; k4 += 4) {
            float4 A[4];
#pragma unroll
            for (int i = 0; i < 4; i++) A[i] = *(const float4*)&xs[rg + i][k4];
#pragma unroll
            for (int kk = 0; kk < 4; kk++) {
                ulonglong2 B0 = *(const ulonglong2*)&ws[k4 + kk][cg];
                ulonglong2 B1 = *(const ulonglong2*)&ws[k4 + kk][cg + 4];
#pragma unroll
                for (int i = 0; i < 4; i++) {
                    float ai = ((const float*)&A[i])[kk];
                    unsigned long long pa = pk(ai, ai);
                    fma2(acc[i][0], pa, B0.x);
                    fma2(acc[i][1], pa, B0.y);
                    fma2(acc[i][2], pa, B1.x);
                    fma2(acc[i][3], pa, B1.y);
                }
            }
        }
        __syncthreads();
        if (t < 15) {
#pragma unroll
            for (int it = 0; it < 4; it++) {
                int slot = tx + it * 256;
                *(float4*)&xs[slot >> 3][(slot & 7) << 2] = xr[it];
            }
#pragma unroll
            for (int it = 0; it < 2; it++) {
                int slot = tx + it * 256;
                *(float4*)&ws[slot >> 4][(slot & 15) << 2] = wr[it];
            }
            __syncthreads();
        }
    }

    // epilogue: fp16 h1 store + fused el/er (this thread's 8 cols == head hc)
    float al[8], ar[8];
#pragma unroll
    for (int c = 0; c < 8; c++) { al[c] = __ldg(al1 + cg + c); ar[c] = __ldg(ar1 + cg + c); }

#pragma unroll
    for (int i = 0; i < 4; i++) {
        int grow = row0 + rg + i;
        if (grow >= n) continue;
        float2 v0 = upk(acc[i][0]), v1 = upk(acc[i][1]);
        float2 v2 = upk(acc[i][2]), v3 = upk(acc[i][3]);
        float h[8] = {v0.x, v0.y, v1.x, v1.y, v2.x, v2.y, v3.x, v3.y};
        float el = 0.f, er = 0.f;
#pragma unroll
        for (int c = 0; c < 8; c++) { el = fmaf(h[c], al[c], el); er = fmaf(h[c], ar[c], er); }
        g_el1h[(size_t)grow * 8 + hc] = __float2half(el);
        g_er1 [(size_t)grow * 8 + hc] = er;
        __half2 p[4];
#pragma unroll
        for (int q = 0; q < 4; q++) p[q] = __floats2half2_rn(h[2*q], h[2*q+1]);
        *(uint4*)(g_h1h + (size_t)grow * D1 + cg) = *(uint4*)p;
    }
}

// ---------------- K3: layer1 CSR aggregation (8 lanes per dst, 1 head/lane) ----------------
__global__ __launch_bounds__(256) void k_agg1(int n) {
    int t = blockIdx.x * 256 + threadIdx.x;
    int d = t >> 3;
    if (d >= n) return;
    int h = t & 7;
    float er = g_er1[(size_t)d * 8 + h];
    int k0 = g_rowstart[d], k1 = g_cursor[d];
    float acc[8] = {0.f, 0.f, 0.f, 0.f, 0.f, 0.f, 0.f, 0.f};
    float denom = 0.f;
    int s = (k0 < k1) ? __ldg(g_sorted + k0) : 0;
    for (int k = k0; k < k1; k++) {
        int s_next = (k + 1 < k1) ? __ldg(g_sorted + k + 1) : 0;
        float el = __half2float(__ldg(g_el1h + (size_t)s * 8 + h));
        float ex = __expf(lrelu(el + er));
        uint4 hv = __ldg((const uint4*)(g_h1h + (size_t)s * D1 + h * 8));
        const __half2* hp = (const __half2*)&hv;
#pragma unroll
        for (int q = 0; q < 4; q++) {
            float2 f = __half22float2(hp[q]);
            acc[2*q]   = fmaf(ex, f.x, acc[2*q]);
            acc[2*q+1] = fmaf(ex, f.y, acc[2*q+1]);
        }
        denom += ex;
        s = s_next;
    }
    float iv = denom > 0.f ? __fdividef(1.f, denom) : 0.f;
    float* op = g_agg1 + (size_t)d * D1 + h * 8;
    *(float4*)(op)     = make_float4(acc[0]*iv, acc[1]*iv, acc[2]*iv, acc[3]*iv);
    *(float4*)(op + 4) = make_float4(acc[4]*iv, acc[5]*iv, acc[6]*iv, acc[7]*iv);
}

// ---------------- K4: node: ELU(agg1 + b1), GEMM2 (64->40), el2/er2, fp16 h2 ----------------
__global__ __launch_bounds__(256) void k_node2(const float* __restrict__ W2,
                                               const float* __restrict__ al2,
                                               const float* __restrict__ ar2,
                                               const float* __restrict__ b1, int n) {
    __shared__ float w2s[64 * 40];
    __shared__ float sal[40], sar[40], sb1[64];
    for (int i = threadIdx.x; i < 64 * 40; i += 256) w2s[i] = W2[i];
    if (threadIdx.x < 40) { sal[threadIdx.x] = al2[threadIdx.x]; sar[threadIdx.x] = ar2[threadIdx.x]; }
    if (threadIdx.x < 64) sb1[threadIdx.x] = b1[threadIdx.x];
    __syncthreads();
    int nid = blockIdx.x * 256 + threadIdx.x;
    if (nid >= n) return;

    float v[64];
    const float4* ap = (const float4*)(g_agg1 + (size_t)nid * D1);
#pragma unroll
    for (int j = 0; j < 16; j++) {
        float4 t = ap[j];
        v[j * 4 + 0] = eluf(t.x + sb1[j * 4 + 0]);
        v[j * 4 + 1] = eluf(t.y + sb1[j * 4 + 1]);
        v[j * 4 + 2] = eluf(t.z + sb1[j * 4 + 2]);
        v[j * 4 + 3] = eluf(t.w + sb1[j * 4 + 3]);
    }
    float ela = 0.f, era = 0.f;
    float hv[40];
    for (int c = 0; c < D2; c++) {
        float acc = 0.f;
#pragma unroll
        for (int k = 0; k < 64; k++) acc = fmaf(v[k], w2s[k * D2 + c], acc);
        hv[c] = acc;
        ela = fmaf(acc, sal[c], ela);
        era = fmaf(acc, sar[c], era);
    }
    __half2 hp[20];
#pragma unroll
    for (int q = 0; q < 20; q++) hp[q] = __floats2half2_rn(hv[2*q], hv[2*q+1]);
    uint4* op = (uint4*)(g_h2h + (size_t)nid * D2);
#pragma unroll
    for (int q = 0; q < 5; q++) op[q] = ((uint4*)hp)[q];
    g_el2h[nid] = __float2half(ela);
    g_er2 [nid] = era;
}

// ---------------- K5: layer2 CSR aggregation (16 lanes/dst, 10 active) ----------------
__global__ __launch_bounds__(256) void k_agg2(int n) {
    int t = blockIdx.x * 256 + threadIdx.x;
    int d = t >> 4;
    if (d >= n) return;
    int j = t & 15;
    if (j >= 10) return;
    float er = g_er2[d];
    int k0 = g_rowstart[d], k1 = g_cursor[d];
    float acc[4] = {0.f, 0.f, 0.f, 0.f};
    float denom = 0.f;
    int s = (k0 < k1) ? __ldg(g_sorted + k0) : 0;
    for (int k = k0; k < k1; k++) {
        int s_next = (k + 1 < k1) ? __ldg(g_sorted + k + 1) : 0;
        float el = __half2float(__ldg(g_el2h + s));
        float ex = __expf(lrelu(el + er));
        uint2 hv = __ldg((const uint2*)(g_h2h + (size_t)s * D2 + j * 4));
        const __half2* hp = (const __half2*)&hv;
        float2 f0 = __half22float2(hp[0]);
        float2 f1 = __half22float2(hp[1]);
        acc[0] = fmaf(ex, f0.x, acc[0]);
        acc[1] = fmaf(ex, f0.y, acc[1]);
        acc[2] = fmaf(ex, f1.x, acc[2]);
        acc[3] = fmaf(ex, f1.y, acc[3]);
        denom += ex;
        s = s_next;
    }
    float iv = denom > 0.f ? __fdividef(1.f, denom) : 0.f;
    *(float4*)(g_agg2 + (size_t)d * D2 + j * 4) =
        make_float4(acc[0]*iv, acc[1]*iv, acc[2]*iv, acc[3]*iv);
}

// ---------------- K6: final: (agg2 + b2) then log_softmax ----------------
__global__ __launch_bounds__(256) void k_lsm(const float* __restrict__ b2,
                                             float* __restrict__ out, int n) {
    __shared__ float sb2[40];
    if (threadIdx.x < 40) sb2[threadIdx.x] = b2[threadIdx.x];
    __syncthreads();
    int nid = blockIdx.x * 256 + threadIdx.x;
    if (nid >= n) return;
    float v[40];
    const float4* ap = (const float4*)(g_agg2 + (size_t)nid * D2);
    float m = -1e30f;
#pragma unroll
    for (int j = 0; j < 10; j++) {
        float4 t = ap[j];
        v[j*4+0] = t.x + sb2[j*4+0];
        v[j*4+1] = t.y + sb2[j*4+1];
        v[j*4+2] = t.z + sb2[j*4+2];
        v[j*4+3] = t.w + sb2[j*4+3];
        m = fmaxf(m, fmaxf(fmaxf(v[j*4+0], v[j*4+1]), fmaxf(v[j*4+2], v[j*4+3])));
    }
    float s = 0.f;
#pragma unroll
    for (int j = 0; j < 40; j++) s += __expf(v[j] - m);
    float lse = m + logf(s);
    float4* op = (float4*)(out + (size_t)nid * D2);
#pragma unroll
    for (int j = 0; j < 10; j++)
        op[j] = make_float4(v[j*4+0] - lse, v[j*4+1] - lse, v[j*4+2] - lse, v[j*4+3] - lse);
}

// ---------------- launch ----------------
extern "C" void kernel_launch(void* const* d_in, const int* in_sizes, int n_in,
                              void* d_out, int out_size) {
    const float* x   = (const float*)d_in[0];
    const int*   src = (const int*)d_in[1];
    const int*   dst = (const int*)d_in[2];
    const float* W1  = (const float*)d_in[3];
    const float* al1 = (const float*)d_in[4];
    const float* ar1 = (const float*)d_in[5];
    const float* b1  = (const float*)d_in[6];
    const float* W2  = (const float*)d_in[7];
    const float* al2 = (const float*)d_in[8];
    const float* ar2 = (const float*)d_in[9];
    const float* b2  = (const float*)d_in[10];

    int n = in_sizes[0] / INF;
    int e = in_sizes[1];

    int nb_node = (n + 255) / 256;
    int nb_edge = (e + 255) / 256;
    int nb_gemm = (n + 127) / 128;
    int nb_agg1 = (n * 8 + 255) / 256;
    int nb_agg2 = (n * 16 + 255) / 256;

    k_zero    <<<nb_node, 256>>>(n);
    k_hist    <<<nb_edge, 256>>>(dst, e);
    k_rowalloc<<<nb_node, 256>>>(n);
    k_scatter <<<nb_edge, 256>>>(src, dst, e);
    k_gemm1   <<<nb_gemm, 256>>>(x, W1, al1, ar1, n);
    k_agg1    <<<nb_agg1, 256>>>(n);
    k_node2   <<<nb_node, 256>>>(W2, al2, ar2, b1, n);
    k_agg2    <<<nb_agg2, 256>>>(n);
    k_lsm     <<<nb_node, 256>>>(b2, (float*)d_out, n);
}

// round 9
// speedup vs baseline: 1.8738x; 1.6454x over previous
#include <cuda_runtime.h>
#include <cuda_fp16.h>

// ---------------- problem constants ----------------
#define NMAX 100000
#define EMAX 1600000
#define INF 512
#define D1 64      // H1*F1 = 8*8
#define H1N 8
#define D2 40      // H2*F2 = 1*40

// ---------------- device scratch ----------------
__device__ __align__(16) __half g_h1h [NMAX * D1];   // fp16 layer1 features (gather payload)
__device__ __align__(16) __half g_el1h[NMAX * H1N];  // fp16 src-side attention
__device__ __align__(16) float  g_er1 [NMAX * H1N];  // fp32 dst-side attention
__device__ __align__(16) float  g_agg1[NMAX * D1];   // normalized layer1 output (pre-bias)
__device__ __align__(16) __half g_h2h [NMAX * D2];   // fp16 layer2 features
__device__ __align__(16) __half g_el2h[NMAX];
__device__ __align__(16) float  g_er2 [NMAX];
__device__ __align__(16) float  g_agg2[NMAX * D2];   // normalized layer2 output (pre-bias)
// CSR scratch
__device__ int g_hist[NMAX];
__device__ int g_rowstart[NMAX];
__device__ int g_cursor[NMAX];
__device__ int g_sorted[EMAX];
__device__ int g_counter;

// ---------------- helpers ----------------
__device__ __forceinline__ float lrelu(float v) { return v >= 0.f ? v : 0.2f * v; }
__device__ __forceinline__ float eluf(float v)  { return v > 0.f ? v : expm1f(v); }

__device__ __forceinline__ unsigned tf32c(float f) {
    unsigned u;
    asm("cvt.rna.tf32.f32 %0, %1;" : "=r"(u) : "f"(f));
    return u;
}
__device__ __forceinline__ void mma_tf32(float* c,
                                         unsigned a0, unsigned a1, unsigned a2, unsigned a3,
                                         unsigned b0, unsigned b1) {
    asm volatile(
        "mma.sync.aligned.m16n8k8.row.col.f32.tf32.tf32.f32 "
        "{%0,%1,%2,%3},{%4,%5,%6,%7},{%8,%9},{%0,%1,%2,%3};"
        : "+f"(c[0]), "+f"(c[1]), "+f"(c[2]), "+f"(c[3])
        : "r"(a0), "r"(a1), "r"(a2), "r"(a3), "r"(b0), "r"(b1));
}

// ---------------- K0: zero hist + counter ----------------
__global__ void k_zero(int n) {
    int i = blockIdx.x * 256 + threadIdx.x;
    if (i < n) g_hist[i] = 0;
    if (i == 0) g_counter = 0;
}

// ---------------- K_hist ----------------
__global__ __launch_bounds__(256) void k_hist(const int* __restrict__ dst, int e) {
    int i = blockIdx.x * 256 + threadIdx.x;
    if (i < e) atomicAdd(&g_hist[dst[i]], 1);
}

// ---------------- K_rowalloc: warp-scanned row offsets ----------------
__global__ __launch_bounds__(256) void k_rowalloc(int n) {
    int d = blockIdx.x * 256 + threadIdx.x;
    int lane = threadIdx.x & 31;
    int c = (d < n) ? g_hist[d] : 0;
    int sum = c;
#pragma unroll
    for (int off = 1; off < 32; off <<= 1) {
        int v = __shfl_up_sync(0xffffffffu, sum, off);
        if (lane >= off) sum += v;
    }
    int total = __shfl_sync(0xffffffffu, sum, 31);
    int base = 0;
    if (lane == 31) base = atomicAdd(&g_counter, total);
    base = __shfl_sync(0xffffffffu, base, 31);
    if (d < n) {
        int st = base + sum - c;
        g_rowstart[d] = st;
        g_cursor[d]   = st;
    }
}

// ---------------- K_scatter ----------------
__global__ __launch_bounds__(256) void k_scatter(const int* __restrict__ src,
                                                 const int* __restrict__ dst, int e) {
    int i = blockIdx.x * 256 + threadIdx.x;
    if (i >= e) return;
    int p = atomicAdd(&g_cursor[dst[i]], 1);
    g_sorted[p] = src[i];
}

// ---------------- K1: h1 = x @ W1 via tf32 mma.sync; fused el1/er1 + fp16 store ----------------
// Block tile: 128 rows x 64 cols, 8 warps (warp w -> rows w*16..w*16+15).
// smem: xs[128][36] tf32 (stride 36 -> conflict-free A frags),
//       ws layout [k/4][n][k%4]  (addr = (k>>2)*256 + n*4 + (k&3)) -> conflict-free B frags.
// Epilogue reuses smem as ds[128][64] fp32.
__global__ __launch_bounds__(256) void k_gemm1(const float* __restrict__ x,
                                               const float* __restrict__ W1,
                                               const float* __restrict__ al1,
                                               const float* __restrict__ ar1, int n) {
    __shared__ __align__(16) float sm[8320];   // 33.3KB: xs(4608) + ws(2048) | ds(8192), al/ar at 8192
    unsigned* xsu = (unsigned*)sm;
    unsigned* wsu = (unsigned*)(sm + 4608);

    const int tx = threadIdx.x;
    const int row0 = blockIdx.x * 128;
    const int warp = tx >> 5;
    const int lane = tx & 31;
    const int g  = lane >> 2;     // group id 0..7
    const int tg = lane & 3;      // thread-in-group 0..3
    const int wrow = warp * 16;

    if (tx < 64) sm[8192 + tx] = al1[tx];
    else if (tx < 128) sm[8192 + tx] = ar1[tx - 64];

    float4 xr[4];
    float4 wr[2];

    // ---- prologue: tile 0 ----
#pragma unroll
    for (int it = 0; it < 4; it++) {
        int slot = tx + it * 256;
        int r = slot >> 3;
        int kk = (slot & 7) << 2;
        int grow = row0 + r;
        xr[it] = (grow < n) ? *(const float4*)(x + (size_t)grow * INF + kk)
                            : make_float4(0.f, 0.f, 0.f, 0.f);
    }
#pragma unroll
    for (int it = 0; it < 2; it++) {
        int slot = tx + it * 256;
        int k = slot >> 4;
        int n4 = (slot & 15) << 2;
        wr[it] = *(const float4*)(W1 + (size_t)k * D1 + n4);
    }
#pragma unroll
    for (int it = 0; it < 4; it++) {
        int slot = tx + it * 256;
        int r = slot >> 3;
        int kk = (slot & 7) << 2;
        *(uint4*)&xsu[r * 36 + kk] =
            make_uint4(tf32c(xr[it].x), tf32c(xr[it].y), tf32c(xr[it].z), tf32c(xr[it].w));
    }
#pragma unroll
    for (int it = 0; it < 2; it++) {
        int slot = tx + it * 256;
        int k = slot >> 4;
        int n4 = (slot & 15) << 2;
        int base = (k >> 2) * 256 + (k & 3);
        wsu[base + (n4 + 0) * 4] = tf32c(wr[it].x);
        wsu[base + (n4 + 1) * 4] = tf32c(wr[it].y);
        wsu[base + (n4 + 2) * 4] = tf32c(wr[it].z);
        wsu[base + (n4 + 3) * 4] = tf32c(wr[it].w);
    }
    __syncthreads();

    float acc[8][4];
#pragma unroll
    for (int j = 0; j < 8; j++)
#pragma unroll
        for (int q = 0; q < 4; q++) acc[j][q] = 0.f;

    for (int tt = 0; tt < 16; tt++) {
        // prefetch next tile into registers
        if (tt < 15) {
            int k0 = (tt + 1) * 32;
#pragma unroll
            for (int it = 0; it < 4; it++) {
                int slot = tx + it * 256;
                int r = slot >> 3;
                int kk = (slot & 7) << 2;
                int grow = row0 + r;
                xr[it] = (grow < n) ? *(const float4*)(x + (size_t)grow * INF + k0 + kk)
                                    : make_float4(0.f, 0.f, 0.f, 0.f);
            }
#pragma unroll
            for (int it = 0; it < 2; it++) {
                int slot = tx + it * 256;
                int k = slot >> 4;
                int n4 = (slot & 15) << 2;
                wr[it] = *(const float4*)(W1 + (size_t)(k0 + k) * D1 + n4);
            }
        }

        // compute current tile: 4 k8 steps
#pragma unroll
        for (int k8 = 0; k8 < 4; k8++) {
            int kb = k8 * 8;
            unsigned a0 = xsu[(wrow + g) * 36 + kb + tg];
            unsigned a1 = xsu[(wrow + g + 8) * 36 + kb + tg];
            unsigned a2 = xsu[(wrow + g) * 36 + kb + tg + 4];
            unsigned a3 = xsu[(wrow + g + 8) * 36 + kb + tg + 4];
            const unsigned* wp = wsu + k8 * 512 + 4 * g + tg;
#pragma unroll
            for (int j = 0; j < 8; j++) {
                unsigned b0 = wp[32 * j];
                unsigned b1 = wp[256 + 32 * j];
                mma_tf32(acc[j], a0, a1, a2, a3, b0, b1);
            }
        }
        __syncthreads();
        if (tt < 15) {
#pragma unroll
            for (int it = 0; it < 4; it++) {
                int slot = tx + it * 256;
                int r = slot >> 3;
                int kk = (slot & 7) << 2;
                *(uint4*)&xsu[r * 36 + kk] =
                    make_uint4(tf32c(xr[it].x), tf32c(xr[it].y), tf32c(xr[it].z), tf32c(xr[it].w));
            }
#pragma unroll
            for (int it = 0; it < 2; it++) {
                int slot = tx + it * 256;
                int k = slot >> 4;
                int n4 = (slot & 15) << 2;
                int base = (k >> 2) * 256 + (k & 3);
                wsu[base + (n4 + 0) * 4] = tf32c(wr[it].x);
                wsu[base + (n4 + 1) * 4] = tf32c(wr[it].y);
                wsu[base + (n4 + 2) * 4] = tf32c(wr[it].z);
                wsu[base + (n4 + 3) * 4] = tf32c(wr[it].w);
            }
            __syncthreads();
        }
    }

    // ---- epilogue: dump accumulators to smem ds[128][64] ----
    float* ds = sm;
#pragma unroll
    for (int j = 0; j < 8; j++) {
        *(float2*)&ds[(wrow + g) * 64 + 8 * j + 2 * tg]     = make_float2(acc[j][0], acc[j][1]);
        *(float2*)&ds[(wrow + g + 8) * 64 + 8 * j + 2 * tg] = make_float2(acc[j][2], acc[j][3]);
    }
    __syncthreads();

    // thread tx: row = tx>>1, half ch = tx&1 -> cols ch*32..+31 (heads 4ch..4ch+3)
    {
        int row = tx >> 1;
        int ch = tx & 1;
        int grow = row0 + row;
        if (grow < n) {
            const float* dp  = ds + row * 64 + ch * 32;
            const float* alp = sm + 8192 + ch * 32;
            const float* arp = sm + 8256 + ch * 32;
            float h[32];
#pragma unroll
            for (int q = 0; q < 8; q++) *(float4*)&h[q * 4] = *(const float4*)(dp + q * 4);

            float elv[4], erv[4];
#pragma unroll
            for (int q = 0; q < 4; q++) {
                float el = 0.f, er = 0.f;
#pragma unroll
                for (int c = 0; c < 8; c++) {
                    el = fmaf(h[q * 8 + c], alp[q * 8 + c], el);
                    er = fmaf(h[q * 8 + c], arp[q * 8 + c], er);
                }
                elv[q] = el; erv[q] = er;
            }
            __half2 ph[16];
#pragma unroll
            for (int q = 0; q < 16; q++) ph[q] = __floats2half2_rn(h[2 * q], h[2 * q + 1]);
            uint4* hop = (uint4*)(g_h1h + (size_t)grow * D1 + ch * 32);
#pragma unroll
            for (int q = 0; q < 4; q++) hop[q] = ((uint4*)ph)[q];

            __half e4[4];
#pragma unroll
            for (int q = 0; q < 4; q++) e4[q] = __float2half(elv[q]);
            *(uint2*)(g_el1h + (size_t)grow * 8 + ch * 4) = *(uint2*)e4;
            *(float4*)(g_er1 + (size_t)grow * 8 + ch * 4) =
                make_float4(erv[0], erv[1], erv[2], erv[3]);
        }
    }
}

// ---------------- K3: layer1 CSR aggregation (8 lanes per dst, 1 head/lane) ----------------
__global__ __launch_bounds__(256) void k_agg1(int n) {
    int t = blockIdx.x * 256 + threadIdx.x;
    int d = t >> 3;
    if (d >= n) return;
    int h = t & 7;
    float er = g_er1[(size_t)d * 8 + h];
    int k0 = g_rowstart[d], k1 = g_cursor[d];
    float acc[8] = {0.f, 0.f, 0.f, 0.f, 0.f, 0.f, 0.f, 0.f};
    float denom = 0.f;
    int s = (k0 < k1) ? __ldg(g_sorted + k0) : 0;
    for (int k = k0; k < k1; k++) {
        int s_next = (k + 1 < k1) ? __ldg(g_sorted + k + 1) : 0;
        float el = __half2float(__ldg(g_el1h + (size_t)s * 8 + h));
        float ex = __expf(lrelu(el + er));
        uint4 hv = __ldg((const uint4*)(g_h1h + (size_t)s * D1 + h * 8));
        const __half2* hp = (const __half2*)&hv;
#pragma unroll
        for (int q = 0; q < 4; q++) {
            float2 f = __half22float2(hp[q]);
            acc[2*q]   = fmaf(ex, f.x, acc[2*q]);
            acc[2*q+1] = fmaf(ex, f.y, acc[2*q+1]);
        }
        denom += ex;
        s = s_next;
    }
    float iv = denom > 0.f ? __fdividef(1.f, denom) : 0.f;
    float* op = g_agg1 + (size_t)d * D1 + h * 8;
    *(float4*)(op)     = make_float4(acc[0]*iv, acc[1]*iv, acc[2]*iv, acc[3]*iv);
    *(float4*)(op + 4) = make_float4(acc[4]*iv, acc[5]*iv, acc[6]*iv, acc[7]*iv);
}

// ---------------- K4: node: ELU(agg1 + b1), GEMM2 (64->40), el2/er2, fp16 h2 ----------------
__global__ __launch_bounds__(256) void k_node2(const float* __restrict__ W2,
                                               const float* __restrict__ al2,
                                               const float* __restrict__ ar2,
                                               const float* __restrict__ b1, int n) {
    __shared__ float w2s[64 * 40];
    __shared__ float sal[40], sar[40], sb1[64];
    for (int i = threadIdx.x; i < 64 * 40; i += 256) w2s[i] = W2[i];
    if (threadIdx.x < 40) { sal[threadIdx.x] = al2[threadIdx.x]; sar[threadIdx.x] = ar2[threadIdx.x]; }
    if (threadIdx.x < 64) sb1[threadIdx.x] = b1[threadIdx.x];
    __syncthreads();
    int nid = blockIdx.x * 256 + threadIdx.x;
    if (nid >= n) return;

    float v[64];
    const float4* ap = (const float4*)(g_agg1 + (size_t)nid * D1);
#pragma unroll
    for (int j = 0; j < 16; j++) {
        float4 t = ap[j];
        v[j * 4 + 0] = eluf(t.x + sb1[j * 4 + 0]);
        v[j * 4 + 1] = eluf(t.y + sb1[j * 4 + 1]);
        v[j * 4 + 2] = eluf(t.z + sb1[j * 4 + 2]);
        v[j * 4 + 3] = eluf(t.w + sb1[j * 4 + 3]);
    }
    float ela = 0.f, era = 0.f;
    float hv[40];
    for (int c = 0; c < D2; c++) {
        float acc = 0.f;
#pragma unroll
        for (int k = 0; k < 64; k++) acc = fmaf(v[k], w2s[k * D2 + c], acc);
        hv[c] = acc;
        ela = fmaf(acc, sal[c], ela);
        era = fmaf(acc, sar[c], era);
    }
    __half2 hp[20];
#pragma unroll
    for (int q = 0; q < 20; q++) hp[q] = __floats2half2_rn(hv[2*q], hv[2*q+1]);
    uint4* op = (uint4*)(g_h2h + (size_t)nid * D2);
#pragma unroll
    for (int q = 0; q < 5; q++) op[q] = ((uint4*)hp)[q];
    g_el2h[nid] = __float2half(ela);
    g_er2 [nid] = era;
}

// ---------------- K5: layer2 CSR aggregation (16 lanes/dst, 10 active) ----------------
__global__ __launch_bounds__(256) void k_agg2(int n) {
    int t = blockIdx.x * 256 + threadIdx.x;
    int d = t >> 4;
    if (d >= n) return;
    int j = t & 15;
    if (j >= 10) return;
    float er = g_er2[d];
    int k0 = g_rowstart[d], k1 = g_cursor[d];
    float acc[4] = {0.f, 0.f, 0.f, 0.f};
    float denom = 0.f;
    int s = (k0 < k1) ? __ldg(g_sorted + k0) : 0;
    for (int k = k0; k < k1; k++) {
        int s_next = (k + 1 < k1) ? __ldg(g_sorted + k + 1) : 0;
        float el = __half2float(__ldg(g_el2h + s));
        float ex = __expf(lrelu(el + er));
        uint2 hv = __ldg((const uint2*)(g_h2h + (size_t)s * D2 + j * 4));
        const __half2* hp = (const __half2*)&hv;
        float2 f0 = __half22float2(hp[0]);
        float2 f1 = __half22float2(hp[1]);
        acc[0] = fmaf(ex, f0.x, acc[0]);
        acc[1] = fmaf(ex, f0.y, acc[1]);
        acc[2] = fmaf(ex, f1.x, acc[2]);
        acc[3] = fmaf(ex, f1.y, acc[3]);
        denom += ex;
        s = s_next;
    }
    float iv = denom > 0.f ? __fdividef(1.f, denom) : 0.f;
    *(float4*)(g_agg2 + (size_t)d * D2 + j * 4) =
        make_float4(acc[0]*iv, acc[1]*iv, acc[2]*iv, acc[3]*iv);
}

// ---------------- K6: final: (agg2 + b2) then log_softmax ----------------
__global__ __launch_bounds__(256) void k_lsm(const float* __restrict__ b2,
                                             float* __restrict__ out, int n) {
    __shared__ float sb2[40];
    if (threadIdx.x < 40) sb2[threadIdx.x] = b2[threadIdx.x];
    __syncthreads();
    int nid = blockIdx.x * 256 + threadIdx.x;
    if (nid >= n) return;
    float v[40];
    const float4* ap = (const float4*)(g_agg2 + (size_t)nid * D2);
    float m = -1e30f;
#pragma unroll
    for (int j = 0; j < 10; j++) {
        float4 t = ap[j];
        v[j*4+0] = t.x + sb2[j*4+0];
        v[j*4+1] = t.y + sb2[j*4+1];
        v[j*4+2] = t.z + sb2[j*4+2];
        v[j*4+3] = t.w + sb2[j*4+3];
        m = fmaxf(m, fmaxf(fmaxf(v[j*4+0], v[j*4+1]), fmaxf(v[j*4+2], v[j*4+3])));
    }
    float s = 0.f;
#pragma unroll
    for (int j = 0; j < 40; j++) s += __expf(v[j] - m);
    float lse = m + logf(s);
    float4* op = (float4*)(out + (size_t)nid * D2);
#pragma unroll
    for (int j = 0; j < 10; j++)
        op[j] = make_float4(v[j*4+0] - lse, v[j*4+1] - lse, v[j*4+2] - lse, v[j*4+3] - lse);
}

// ---------------- launch ----------------
extern "C" void kernel_launch(void* const* d_in, const int* in_sizes, int n_in,
                              void* d_out, int out_size) {
    const float* x   = (const float*)d_in[0];
    const int*   src = (const int*)d_in[1];
    const int*   dst = (const int*)d_in[2];
    const float* W1  = (const float*)d_in[3];
    const float* al1 = (const float*)d_in[4];
    const float* ar1 = (const float*)d_in[5];
    const float* b1  = (const float*)d_in[6];
    const float* W2  = (const float*)d_in[7];
    const float* al2 = (const float*)d_in[8];
    const float* ar2 = (const float*)d_in[9];
    const float* b2  = (const float*)d_in[10];

    int n = in_sizes[0] / INF;
    int e = in_sizes[1];

    int nb_node = (n + 255) / 256;
    int nb_edge = (e + 255) / 256;
    int nb_gemm = (n + 127) / 128;
    int nb_agg1 = (n * 8 + 255) / 256;
    int nb_agg2 = (n * 16 + 255) / 256;

    k_zero    <<<nb_node, 256>>>(n);
    k_hist    <<<nb_edge, 256>>>(dst, e);
    k_rowalloc<<<nb_node, 256>>>(n);
    k_scatter <<<nb_edge, 256>>>(src, dst, e);
    k_gemm1   <<<nb_gemm, 256>>>(x, W1, al1, ar1, n);
    k_agg1    <<<nb_agg1, 256>>>(n);
    k_node2   <<<nb_node, 256>>>(W2, al2, ar2, b1, n);
    k_agg2    <<<nb_agg2, 256>>>(n);
    k_lsm     <<<nb_node, 256>>>(b2, (float*)d_out, n);
}

// round 10
// speedup vs baseline: 2.1822x; 1.1646x over previous
#include <cuda_runtime.h>
#include <cuda_fp16.h>

// ---------------- problem constants ----------------
#define NMAX 100000
#define EMAX 1600000
#define INF 512
#define D1 64      // H1*F1 = 8*8
#define H1N 8
#define D2 40      // H2*F2 = 1*40

// ---------------- device scratch ----------------
__device__ __align__(16) __half g_h1h [NMAX * D1];   // fp16 layer1 features (gather payload)
__device__ __align__(16) __half g_el1h[NMAX * H1N];  // fp16 src-side attention
__device__ __align__(16) float  g_er1 [NMAX * H1N];  // fp32 dst-side attention
__device__ __align__(16) float  g_agg1[NMAX * D1];   // normalized layer1 output (pre-bias)
__device__ __align__(16) __half g_h2h [NMAX * D2];   // fp16 layer2 features
__device__ __align__(16) __half g_el2h[NMAX];
__device__ __align__(16) float  g_er2 [NMAX];
__device__ __align__(16) float  g_agg2[NMAX * D2];   // normalized layer2 output (pre-bias)
// CSR scratch
__device__ int g_hist[NMAX];
__device__ int g_rowstart[NMAX];
__device__ int g_cursor[NMAX];
__device__ int g_sorted[EMAX];
__device__ int g_counter;

// ---------------- helpers ----------------
__device__ __forceinline__ float lrelu(float v) { return v >= 0.f ? v : 0.2f * v; }
__device__ __forceinline__ float eluf(float v)  { return v > 0.f ? v : expm1f(v); }

__device__ __forceinline__ unsigned tf32c(float f) {
    unsigned u;
    asm("cvt.rna.tf32.f32 %0, %1;" : "=r"(u) : "f"(f));
    return u;
}
__device__ __forceinline__ void mma_tf32(float* c,
                                         unsigned a0, unsigned a1, unsigned a2, unsigned a3,
                                         unsigned b0, unsigned b1) {
    asm volatile(
        "mma.sync.aligned.m16n8k8.row.col.f32.tf32.tf32.f32 "
        "{%0,%1,%2,%3},{%4,%5,%6,%7},{%8,%9},{%0,%1,%2,%3};"
        : "+f"(c[0]), "+f"(c[1]), "+f"(c[2]), "+f"(c[3])
        : "r"(a0), "r"(a1), "r"(a2), "r"(a3), "r"(b0), "r"(b1));
}

// ---------------- K0: zero hist + counter ----------------
__global__ void k_zero(int n) {
    int i = blockIdx.x * 256 + threadIdx.x;
    if (i < n) g_hist[i] = 0;
    if (i == 0) g_counter = 0;
}

// ---------------- K_hist ----------------
__global__ __launch_bounds__(256) void k_hist(const int* __restrict__ dst, int e) {
    int i = blockIdx.x * 256 + threadIdx.x;
    if (i < e) atomicAdd(&g_hist[dst[i]], 1);
}

// ---------------- K_rowalloc: warp-scanned row offsets ----------------
__global__ __launch_bounds__(256) void k_rowalloc(int n) {
    int d = blockIdx.x * 256 + threadIdx.x;
    int lane = threadIdx.x & 31;
    int c = (d < n) ? g_hist[d] : 0;
    int sum = c;
#pragma unroll
    for (int off = 1; off < 32; off <<= 1) {
        int v = __shfl_up_sync(0xffffffffu, sum, off);
        if (lane >= off) sum += v;
    }
    int total = __shfl_sync(0xffffffffu, sum, 31);
    int base = 0;
    if (lane == 31) base = atomicAdd(&g_counter, total);
    base = __shfl_sync(0xffffffffu, base, 31);
    if (d < n) {
        int st = base + sum - c;
        g_rowstart[d] = st;
        g_cursor[d]   = st;
    }
}

// ---------------- K_scatter ----------------
__global__ __launch_bounds__(256) void k_scatter(const int* __restrict__ src,
                                                 const int* __restrict__ dst, int e) {
    int i = blockIdx.x * 256 + threadIdx.x;
    if (i >= e) return;
    int p = atomicAdd(&g_cursor[dst[i]], 1);
    g_sorted[p] = src[i];
}

// ---------------- K1: h1 = x @ W1 via tf32 mma.sync; fused el1/er1 + fp16 store ----------------
__global__ __launch_bounds__(256) void k_gemm1(const float* __restrict__ x,
                                               const float* __restrict__ W1,
                                               const float* __restrict__ al1,
                                               const float* __restrict__ ar1, int n) {
    __shared__ __align__(16) float sm[8320];   // xs(4608) + ws(2048) | ds(8192), al/ar at 8192
    unsigned* xsu = (unsigned*)sm;
    unsigned* wsu = (unsigned*)(sm + 4608);

    const int tx = threadIdx.x;
    const int row0 = blockIdx.x * 128;
    const int warp = tx >> 5;
    const int lane = tx & 31;
    const int g  = lane >> 2;
    const int tg = lane & 3;
    const int wrow = warp * 16;

    if (tx < 64) sm[8192 + tx] = al1[tx];
    else if (tx < 128) sm[8192 + tx] = ar1[tx - 64];

    float4 xr[4];
    float4 wr[2];

#pragma unroll
    for (int it = 0; it < 4; it++) {
        int slot = tx + it * 256;
        int r = slot >> 3;
        int kk = (slot & 7) << 2;
        int grow = row0 + r;
        xr[it] = (grow < n) ? *(const float4*)(x + (size_t)grow * INF + kk)
                            : make_float4(0.f, 0.f, 0.f, 0.f);
    }
#pragma unroll
    for (int it = 0; it < 2; it++) {
        int slot = tx + it * 256;
        int k = slot >> 4;
        int n4 = (slot & 15) << 2;
        wr[it] = *(const float4*)(W1 + (size_t)k * D1 + n4);
    }
#pragma unroll
    for (int it = 0; it < 4; it++) {
        int slot = tx + it * 256;
        int r = slot >> 3;
        int kk = (slot & 7) << 2;
        *(uint4*)&xsu[r * 36 + kk] =
            make_uint4(tf32c(xr[it].x), tf32c(xr[it].y), tf32c(xr[it].z), tf32c(xr[it].w));
    }
#pragma unroll
    for (int it = 0; it < 2; it++) {
        int slot = tx + it * 256;
        int k = slot >> 4;
        int n4 = (slot & 15) << 2;
        int base = (k >> 2) * 256 + (k & 3);
        wsu[base + (n4 + 0) * 4] = tf32c(wr[it].x);
        wsu[base + (n4 + 1) * 4] = tf32c(wr[it].y);
        wsu[base + (n4 + 2) * 4] = tf32c(wr[it].z);
        wsu[base + (n4 + 3) * 4] = tf32c(wr[it].w);
    }
    __syncthreads();

    float acc[8][4];
#pragma unroll
    for (int j = 0; j < 8; j++)
#pragma unroll
        for (int q = 0; q < 4; q++) acc[j][q] = 0.f;

    for (int tt = 0; tt < 16; tt++) {
        if (tt < 15) {
            int k0 = (tt + 1) * 32;
#pragma unroll
            for (int it = 0; it < 4; it++) {
                int slot = tx + it * 256;
                int r = slot >> 3;
                int kk = (slot & 7) << 2;
                int grow = row0 + r;
                xr[it] = (grow < n) ? *(const float4*)(x + (size_t)grow * INF + k0 + kk)
                                    : make_float4(0.f, 0.f, 0.f, 0.f);
            }
#pragma unroll
            for (int it = 0; it < 2; it++) {
                int slot = tx + it * 256;
                int k = slot >> 4;
                int n4 = (slot & 15) << 2;
                wr[it] = *(const float4*)(W1 + (size_t)(k0 + k) * D1 + n4);
            }
        }

#pragma unroll
        for (int k8 = 0; k8 < 4; k8++) {
            int kb = k8 * 8;
            unsigned a0 = xsu[(wrow + g) * 36 + kb + tg];
            unsigned a1 = xsu[(wrow + g + 8) * 36 + kb + tg];
            unsigned a2 = xsu[(wrow + g) * 36 + kb + tg + 4];
            unsigned a3 = xsu[(wrow + g + 8) * 36 + kb + tg + 4];
            const unsigned* wp = wsu + k8 * 512 + 4 * g + tg;
#pragma unroll
            for (int j = 0; j < 8; j++) {
                unsigned b0 = wp[32 * j];
                unsigned b1 = wp[256 + 32 * j];
                mma_tf32(acc[j], a0, a1, a2, a3, b0, b1);
            }
        }
        __syncthreads();
        if (tt < 15) {
#pragma unroll
            for (int it = 0; it < 4; it++) {
                int slot = tx + it * 256;
                int r = slot >> 3;
                int kk = (slot & 7) << 2;
                *(uint4*)&xsu[r * 36 + kk] =
                    make_uint4(tf32c(xr[it].x), tf32c(xr[it].y), tf32c(xr[it].z), tf32c(xr[it].w));
            }
#pragma unroll
            for (int it = 0; it < 2; it++) {
                int slot = tx + it * 256;
                int k = slot >> 4;
                int n4 = (slot & 15) << 2;
                int base = (k >> 2) * 256 + (k & 3);
                wsu[base + (n4 + 0) * 4] = tf32c(wr[it].x);
                wsu[base + (n4 + 1) * 4] = tf32c(wr[it].y);
                wsu[base + (n4 + 2) * 4] = tf32c(wr[it].z);
                wsu[base + (n4 + 3) * 4] = tf32c(wr[it].w);
            }
            __syncthreads();
        }
    }

    float* ds = sm;
#pragma unroll
    for (int j = 0; j < 8; j++) {
        *(float2*)&ds[(wrow + g) * 64 + 8 * j + 2 * tg]     = make_float2(acc[j][0], acc[j][1]);
        *(float2*)&ds[(wrow + g + 8) * 64 + 8 * j + 2 * tg] = make_float2(acc[j][2], acc[j][3]);
    }
    __syncthreads();

    {
        int row = tx >> 1;
        int ch = tx & 1;
        int grow = row0 + row;
        if (grow < n) {
            const float* dp  = ds + row * 64 + ch * 32;
            const float* alp = sm + 8192 + ch * 32;
            const float* arp = sm + 8256 + ch * 32;
            float h[32];
#pragma unroll
            for (int q = 0; q < 8; q++) *(float4*)&h[q * 4] = *(const float4*)(dp + q * 4);

            float elv[4], erv[4];
#pragma unroll
            for (int q = 0; q < 4; q++) {
                float el = 0.f, er = 0.f;
#pragma unroll
                for (int c = 0; c < 8; c++) {
                    el = fmaf(h[q * 8 + c], alp[q * 8 + c], el);
                    er = fmaf(h[q * 8 + c], arp[q * 8 + c], er);
                }
                elv[q] = el; erv[q] = er;
            }
            __half2 ph[16];
#pragma unroll
            for (int q = 0; q < 16; q++) ph[q] = __floats2half2_rn(h[2 * q], h[2 * q + 1]);
            uint4* hop = (uint4*)(g_h1h + (size_t)grow * D1 + ch * 32);
#pragma unroll
            for (int q = 0; q < 4; q++) hop[q] = ((uint4*)ph)[q];

            __half e4[4];
#pragma unroll
            for (int q = 0; q < 4; q++) e4[q] = __float2half(elv[q]);
            *(uint2*)(g_el1h + (size_t)grow * 8 + ch * 4) = *(uint2*)e4;
            *(float4*)(g_er1 + (size_t)grow * 8 + ch * 4) =
                make_float4(erv[0], erv[1], erv[2], erv[3]);
        }
    }
}

// ---------------- K3: layer1 CSR aggregation (8 lanes per dst), unrolled x2 ----------------
__global__ __launch_bounds__(256) void k_agg1(int n) {
    int t = blockIdx.x * 256 + threadIdx.x;
    int d = t >> 3;
    if (d >= n) return;
    int h = t & 7;
    float er = g_er1[(size_t)d * 8 + h];
    int k0 = g_rowstart[d], k1 = g_cursor[d];
    float acc[8] = {0.f, 0.f, 0.f, 0.f, 0.f, 0.f, 0.f, 0.f};
    float denom = 0.f;
    int k = k0;
    for (; k + 2 <= k1; k += 2) {
        int sA = __ldg(g_sorted + k);
        int sB = __ldg(g_sorted + k + 1);
        float elA = __half2float(__ldg(g_el1h + (size_t)sA * 8 + h));
        float elB = __half2float(__ldg(g_el1h + (size_t)sB * 8 + h));
        uint4 hvA = __ldg((const uint4*)(g_h1h + (size_t)sA * D1 + h * 8));
        uint4 hvB = __ldg((const uint4*)(g_h1h + (size_t)sB * D1 + h * 8));
        float exA = __expf(lrelu(elA + er));
        float exB = __expf(lrelu(elB + er));
        const __half2* hpA = (const __half2*)&hvA;
        const __half2* hpB = (const __half2*)&hvB;
#pragma unroll
        for (int q = 0; q < 4; q++) {
            float2 fA = __half22float2(hpA[q]);
            float2 fB = __half22float2(hpB[q]);
            acc[2*q]   = fmaf(exA, fA.x, acc[2*q]);
            acc[2*q+1] = fmaf(exA, fA.y, acc[2*q+1]);
            acc[2*q]   = fmaf(exB, fB.x, acc[2*q]);
            acc[2*q+1] = fmaf(exB, fB.y, acc[2*q+1]);
        }
        denom += exA + exB;
    }
    if (k < k1) {
        int s = __ldg(g_sorted + k);
        float el = __half2float(__ldg(g_el1h + (size_t)s * 8 + h));
        float ex = __expf(lrelu(el + er));
        uint4 hv = __ldg((const uint4*)(g_h1h + (size_t)s * D1 + h * 8));
        const __half2* hp = (const __half2*)&hv;
#pragma unroll
        for (int q = 0; q < 4; q++) {
            float2 f = __half22float2(hp[q]);
            acc[2*q]   = fmaf(ex, f.x, acc[2*q]);
            acc[2*q+1] = fmaf(ex, f.y, acc[2*q+1]);
        }
        denom += ex;
    }
    float iv = denom > 0.f ? __fdividef(1.f, denom) : 0.f;
    float* op = g_agg1 + (size_t)d * D1 + h * 8;
    *(float4*)(op)     = make_float4(acc[0]*iv, acc[1]*iv, acc[2]*iv, acc[3]*iv);
    *(float4*)(op + 4) = make_float4(acc[4]*iv, acc[5]*iv, acc[6]*iv, acc[7]*iv);
}

// ---------------- K4: node: ELU(agg1 + b1), GEMM2 (64->40) vectorized, el2/er2, fp16 h2 ----------------
__global__ __launch_bounds__(256) void k_node2(const float* __restrict__ W2,
                                               const float* __restrict__ al2,
                                               const float* __restrict__ ar2,
                                               const float* __restrict__ b1, int n) {
    __shared__ __align__(16) float w2s[64 * 40];
    __shared__ float sal[40], sar[40], sb1[64];
    for (int i = threadIdx.x; i < 64 * 40; i += 256) w2s[i] = W2[i];
    if (threadIdx.x < 40) { sal[threadIdx.x] = al2[threadIdx.x]; sar[threadIdx.x] = ar2[threadIdx.x]; }
    if (threadIdx.x < 64) sb1[threadIdx.x] = b1[threadIdx.x];
    __syncthreads();
    int nid = blockIdx.x * 256 + threadIdx.x;
    if (nid >= n) return;

    float acc[40];
#pragma unroll
    for (int c = 0; c < 40; c++) acc[c] = 0.f;

    const float4* ap = (const float4*)(g_agg1 + (size_t)nid * D1);
    for (int j = 0; j < 16; j++) {          // dynamic loop: acc stays in regs (const idx)
        float4 tv = ap[j];
        const float* bp = sb1 + j * 4;
        float v0 = eluf(tv.x + bp[0]);
        float v1 = eluf(tv.y + bp[1]);
        float v2 = eluf(tv.z + bp[2]);
        float v3 = eluf(tv.w + bp[3]);
        const float4* w0 = (const float4*)&w2s[(j * 4 + 0) * 40];
        const float4* w1 = (const float4*)&w2s[(j * 4 + 1) * 40];
        const float4* w2 = (const float4*)&w2s[(j * 4 + 2) * 40];
        const float4* w3 = (const float4*)&w2s[(j * 4 + 3) * 40];
#pragma unroll
        for (int q = 0; q < 10; q++) {
            float4 a = w0[q], b = w1[q], c = w2[q], d = w3[q];
            acc[q*4+0] = fmaf(v0, a.x, fmaf(v1, b.x, fmaf(v2, c.x, fmaf(v3, d.x, acc[q*4+0]))));
            acc[q*4+1] = fmaf(v0, a.y, fmaf(v1, b.y, fmaf(v2, c.y, fmaf(v3, d.y, acc[q*4+1]))));
            acc[q*4+2] = fmaf(v0, a.z, fmaf(v1, b.z, fmaf(v2, c.z, fmaf(v3, d.z, acc[q*4+2]))));
            acc[q*4+3] = fmaf(v0, a.w, fmaf(v1, b.w, fmaf(v2, c.w, fmaf(v3, d.w, acc[q*4+3]))));
        }
    }

    float ela = 0.f, era = 0.f;
#pragma unroll
    for (int c = 0; c < 40; c++) {
        ela = fmaf(acc[c], sal[c], ela);
        era = fmaf(acc[c], sar[c], era);
    }
    __half2 hp[20];
#pragma unroll
    for (int q = 0; q < 20; q++) hp[q] = __floats2half2_rn(acc[2*q], acc[2*q+1]);
    uint4* op = (uint4*)(g_h2h + (size_t)nid * D2);
#pragma unroll
    for (int q = 0; q < 5; q++) op[q] = ((uint4*)hp)[q];
    g_el2h[nid] = __float2half(ela);
    g_er2 [nid] = era;
}

// ---------------- K5: layer2 CSR aggregation (16 lanes/dst, 10 active), unrolled x2 ----------------
__global__ __launch_bounds__(256) void k_agg2(int n) {
    int t = blockIdx.x * 256 + threadIdx.x;
    int d = t >> 4;
    if (d >= n) return;
    int j = t & 15;
    if (j >= 10) return;
    float er = g_er2[d];
    int k0 = g_rowstart[d], k1 = g_cursor[d];
    float acc[4] = {0.f, 0.f, 0.f, 0.f};
    float denom = 0.f;
    int k = k0;
    for (; k + 2 <= k1; k += 2) {
        int sA = __ldg(g_sorted + k);
        int sB = __ldg(g_sorted + k + 1);
        float elA = __half2float(__ldg(g_el2h + sA));
        float elB = __half2float(__ldg(g_el2h + sB));
        uint2 hvA = __ldg((const uint2*)(g_h2h + (size_t)sA * D2 + j * 4));
        uint2 hvB = __ldg((const uint2*)(g_h2h + (size_t)sB * D2 + j * 4));
        float exA = __expf(lrelu(elA + er));
        float exB = __expf(lrelu(elB + er));
        const __half2* hpA = (const __half2*)&hvA;
        const __half2* hpB = (const __half2*)&hvB;
        float2 fA0 = __half22float2(hpA[0]), fA1 = __half22float2(hpA[1]);
        float2 fB0 = __half22float2(hpB[0]), fB1 = __half22float2(hpB[1]);
        acc[0] = fmaf(exA, fA0.x, fmaf(exB, fB0.x, acc[0]));
        acc[1] = fmaf(exA, fA0.y, fmaf(exB, fB0.y, acc[1]));
        acc[2] = fmaf(exA, fA1.x, fmaf(exB, fB1.x, acc[2]));
        acc[3] = fmaf(exA, fA1.y, fmaf(exB, fB1.y, acc[3]));
        denom += exA + exB;
    }
    if (k < k1) {
        int s = __ldg(g_sorted + k);
        float el = __half2float(__ldg(g_el2h + s));
        float ex = __expf(lrelu(el + er));
        uint2 hv = __ldg((const uint2*)(g_h2h + (size_t)s * D2 + j * 4));
        const __half2* hp = (const __half2*)&hv;
        float2 f0 = __half22float2(hp[0]);
        float2 f1 = __half22float2(hp[1]);
        acc[0] = fmaf(ex, f0.x, acc[0]);
        acc[1] = fmaf(ex, f0.y, acc[1]);
        acc[2] = fmaf(ex, f1.x, acc[2]);
        acc[3] = fmaf(ex, f1.y, acc[3]);
        denom += ex;
    }
    float iv = denom > 0.f ? __fdividef(1.f, denom) : 0.f;
    *(float4*)(g_agg2 + (size_t)d * D2 + j * 4) =
        make_float4(acc[0]*iv, acc[1]*iv, acc[2]*iv, acc[3]*iv);
}

// ---------------- K6: final: (agg2 + b2) then log_softmax ----------------
__global__ __launch_bounds__(256) void k_lsm(const float* __restrict__ b2,
                                             float* __restrict__ out, int n) {
    __shared__ float sb2[40];
    if (threadIdx.x < 40) sb2[threadIdx.x] = b2[threadIdx.x];
    __syncthreads();
    int nid = blockIdx.x * 256 + threadIdx.x;
    if (nid >= n) return;
    float v[40];
    const float4* ap = (const float4*)(g_agg2 + (size_t)nid * D2);
    float m = -1e30f;
#pragma unroll
    for (int j = 0; j < 10; j++) {
        float4 t = ap[j];
        v[j*4+0] = t.x + sb2[j*4+0];
        v[j*4+1] = t.y + sb2[j*4+1];
        v[j*4+2] = t.z + sb2[j*4+2];
        v[j*4+3] = t.w + sb2[j*4+3];
        m = fmaxf(m, fmaxf(fmaxf(v[j*4+0], v[j*4+1]), fmaxf(v[j*4+2], v[j*4+3])));
    }
    float s = 0.f;
#pragma unroll
    for (int j = 0; j < 40; j++) s += __expf(v[j] - m);
    float lse = m + logf(s);
    float4* op = (float4*)(out + (size_t)nid * D2);
#pragma unroll
    for (int j = 0; j < 10; j++)
        op[j] = make_float4(v[j*4+0] - lse, v[j*4+1] - lse, v[j*4+2] - lse, v[j*4+3] - lse);
}

// ---------------- launch ----------------
extern "C" void kernel_launch(void* const* d_in, const int* in_sizes, int n_in,
                              void* d_out, int out_size) {
    const float* x   = (const float*)d_in[0];
    const int*   src = (const int*)d_in[1];
    const int*   dst = (const int*)d_in[2];
    const float* W1  = (const float*)d_in[3];
    const float* al1 = (const float*)d_in[4];
    const float* ar1 = (const float*)d_in[5];
    const float* b1  = (const float*)d_in[6];
    const float* W2  = (const float*)d_in[7];
    const float* al2 = (const float*)d_in[8];
    const float* ar2 = (const float*)d_in[9];
    const float* b2  = (const float*)d_in[10];

    int n = in_sizes[0] / INF;
    int e = in_sizes[1];

    int nb_node = (n + 255) / 256;
    int nb_edge = (e + 255) / 256;
    int nb_gemm = (n + 127) / 128;
    int nb_agg1 = (n * 8 + 255) / 256;
    int nb_agg2 = (n * 16 + 255) / 256;

    // One-time side stream + events for fork-join inside graph capture.
    // (Created on the first, non-captured, correctness call; reused thereafter.
    //  No device memory is allocated and the captured work is identical per call.)
    static cudaStream_t s_side = nullptr;
    static cudaEvent_t  s_evA  = nullptr;
    static cudaEvent_t  s_evB  = nullptr;
    if (s_side == nullptr) {
        cudaStreamCreateWithFlags(&s_side, cudaStreamNonBlocking);
        cudaEventCreateWithFlags(&s_evA, cudaEventDisableTiming);
        cudaEventCreateWithFlags(&s_evB, cudaEventDisableTiming);
    }

    // fork: CSR build on side stream, GEMM1 on main stream
    cudaEventRecord(s_evA, 0);
    cudaStreamWaitEvent(s_side, s_evA, 0);

    k_zero    <<<nb_node, 256, 0, s_side>>>(n);
    k_hist    <<<nb_edge, 256, 0, s_side>>>(dst, e);
    k_rowalloc<<<nb_node, 256, 0, s_side>>>(n);
    k_scatter <<<nb_edge, 256, 0, s_side>>>(src, dst, e);
    cudaEventRecord(s_evB, s_side);

    k_gemm1   <<<nb_gemm, 256>>>(x, W1, al1, ar1, n);

    // join
    cudaStreamWaitEvent(0, s_evB, 0);

    k_agg1    <<<nb_agg1, 256>>>(n);
    k_node2   <<<nb_node, 256>>>(W2, al2, ar2, b1, n);
    k_agg2    <<<nb_agg2, 256>>>(n);
    k_lsm     <<<nb_node, 256>>>(b2, (float*)d_out, n);
}